// round 1
// baseline (speedup 1.0000x reference)
#include <cuda_runtime.h>
#include <math.h>

// Problem constants
#define BATCH 2
#define SEQ   2048
#define DIM   1024
#define NHEAD 16
#define HDIM  64
#define MROWS (BATCH * SEQ)   // 4096

// Scratch (no allocations allowed -> __device__ globals)
__device__ float g_h  [MROWS * DIM];
__device__ float g_qkv[MROWS * 3 * DIM];
__device__ float g_att[MROWS * DIM];
__device__ float g_x1 [MROWS * DIM];
__device__ float g_h2 [MROWS * DIM];
__device__ float g_fc [MROWS * 4 * DIM];

// ---------------------------------------------------------------------------
// LayerNorm over last dim (=1024). One block per row, 256 threads, float4.
// ---------------------------------------------------------------------------
__global__ __launch_bounds__(256) void ln_kernel(
    const float* __restrict__ x, const float* __restrict__ g,
    const float* __restrict__ b, float* __restrict__ y)
{
    __shared__ float sh[16];
    int row = blockIdx.x;
    int t = threadIdx.x;
    const float4* xr = (const float4*)(x + (size_t)row * DIM);
    float4 v = xr[t];
    float s  = v.x + v.y + v.z + v.w;
    float s2 = v.x*v.x + v.y*v.y + v.z*v.z + v.w*v.w;
    #pragma unroll
    for (int o = 16; o > 0; o >>= 1) {
        s  += __shfl_xor_sync(0xffffffffu, s,  o);
        s2 += __shfl_xor_sync(0xffffffffu, s2, o);
    }
    if ((t & 31) == 0) { sh[t >> 5] = s; sh[8 + (t >> 5)] = s2; }
    __syncthreads();
    if (t < 32) {
        float a  = (t < 8) ? sh[t]     : 0.0f;
        float a2 = (t < 8) ? sh[8 + t] : 0.0f;
        #pragma unroll
        for (int o = 4; o > 0; o >>= 1) {
            a  += __shfl_xor_sync(0xffffffffu, a,  o);
            a2 += __shfl_xor_sync(0xffffffffu, a2, o);
        }
        if (t == 0) { sh[0] = a; sh[1] = a2; }
    }
    __syncthreads();
    float mean = sh[0] * (1.0f / DIM);
    float var  = sh[1] * (1.0f / DIM) - mean * mean;
    float rstd = rsqrtf(var + 1e-5f);
    float4 gg = ((const float4*)g)[t];
    float4 bb = ((const float4*)b)[t];
    float4 o4;
    o4.x = (v.x - mean) * rstd * gg.x + bb.x;
    o4.y = (v.y - mean) * rstd * gg.y + bb.y;
    o4.z = (v.z - mean) * rstd * gg.z + bb.z;
    o4.w = (v.w - mean) * rstd * gg.w + bb.w;
    ((float4*)(y + (size_t)row * DIM))[t] = o4;
}

// ---------------------------------------------------------------------------
// Tiled fp32 GEMM: C = act(A[MxK] @ B[KxN] + bias (+ residual))
// 128x128 block tile, BK=16, 256 threads, 8x8 microtile per thread.
// ACT: 0 = none, 1 = exact GELU. residual may be null.
// All of M, N, K are multiples of 128 here (no bounds checks).
// ---------------------------------------------------------------------------
template <int ACT>
__global__ __launch_bounds__(256) void gemm128(
    const float* __restrict__ A, const float* __restrict__ B,
    const float* __restrict__ bias, const float* __restrict__ res,
    float* __restrict__ C, int M, int N, int K)
{
    __shared__ float As[16][132];   // transposed: As[k][m]
    __shared__ float Bs[16][132];   // Bs[k][n]

    int tid  = threadIdx.x;
    int bx   = blockIdx.x;   // N tile
    int by   = blockIdx.y;   // M tile
    int rowg = tid >> 4;     // 0..15
    int colg = tid & 15;     // 0..15

    const float* Ab = A + (size_t)(by * 128) * K;
    const float* Bb = B + (size_t)bx * 128;

    float acc[8][8];
    #pragma unroll
    for (int i = 0; i < 8; i++)
        #pragma unroll
        for (int j = 0; j < 8; j++) acc[i][j] = 0.0f;

    for (int k0 = 0; k0 < K; k0 += 16) {
        // Load A tile 128x16 (512 float4): s = i*256 + tid
        #pragma unroll
        for (int i = 0; i < 2; i++) {
            int s = i * 256 + tid;
            int row = s >> 2;            // 0..127
            int kq  = (s & 3) * 4;       // 0,4,8,12
            float4 v = *(const float4*)(Ab + (size_t)row * K + k0 + kq);
            As[kq + 0][row] = v.x;
            As[kq + 1][row] = v.y;
            As[kq + 2][row] = v.z;
            As[kq + 3][row] = v.w;
        }
        // Load B tile 16x128 (512 float4)
        #pragma unroll
        for (int i = 0; i < 2; i++) {
            int s = i * 256 + tid;
            int kr = s >> 5;             // 0..15
            int nq = (s & 31) * 4;       // 0..124
            float4 v = *(const float4*)(Bb + (size_t)(k0 + kr) * N + nq);
            *(float4*)&Bs[kr][nq] = v;
        }
        __syncthreads();
        #pragma unroll
        for (int k = 0; k < 16; k++) {
            float4 a0 = *(const float4*)&As[k][rowg * 8];
            float4 a1 = *(const float4*)&As[k][rowg * 8 + 4];
            float4 b0 = *(const float4*)&Bs[k][colg * 8];
            float4 b1 = *(const float4*)&Bs[k][colg * 8 + 4];
            float av[8] = {a0.x,a0.y,a0.z,a0.w,a1.x,a1.y,a1.z,a1.w};
            float bv[8] = {b0.x,b0.y,b0.z,b0.w,b1.x,b1.y,b1.z,b1.w};
            #pragma unroll
            for (int i = 0; i < 8; i++)
                #pragma unroll
                for (int j = 0; j < 8; j++)
                    acc[i][j] += av[i] * bv[j];
        }
        __syncthreads();
    }

    int row0 = by * 128 + rowg * 8;
    int col0 = bx * 128 + colg * 8;
    #pragma unroll
    for (int i = 0; i < 8; i++) {
        float out[8];
        #pragma unroll
        for (int j = 0; j < 8; j++) {
            float v = acc[i][j] + bias[col0 + j];
            if (res) v += res[(size_t)(row0 + i) * N + col0 + j];
            if (ACT == 1) v = 0.5f * v * (1.0f + erff(v * 0.70710678118654752f));
            out[j] = v;
        }
        *(float4*)(C + (size_t)(row0 + i) * N + col0)     = *(float4*)&out[0];
        *(float4*)(C + (size_t)(row0 + i) * N + col0 + 4) = *(float4*)&out[4];
    }
}

// ---------------------------------------------------------------------------
// Flash attention, fp32. One block per (query-tile 64, b*h).
// qkv layout: [B*S, 3*DIM]; q at col h*64, k at DIM + h*64, v at 2*DIM + h*64.
// Output: [B*S, DIM] at col h*64.
// ---------------------------------------------------------------------------
#define ATTN_SMEM ((3 * 64 * 65 + 64 * 64) * 4)

__global__ __launch_bounds__(256) void attn_kernel(
    const float* __restrict__ qkv, float* __restrict__ out)
{
    extern __shared__ float sm[];
    float* Qs = sm;                  // [64][65]
    float* Ks = Qs + 64 * 65;        // [64][65]
    float* Ps = Ks + 64 * 65;        // [64][65]
    float* Vs = Ps + 64 * 65;        // [64][64]

    const int D3 = 3 * DIM;
    int qb = blockIdx.x;             // 0..31
    int bh = blockIdx.y;             // 0..31
    int b  = bh >> 4;
    int h  = bh & 15;
    int t  = threadIdx.x;
    int ty = t >> 4;                 // 0..15 (4 query rows each)
    int tx = t & 15;                 // 0..15 (4 cols each)

    // Load Q tile (64 rows x 64 cols)
    const float* qbase = qkv + ((size_t)(b * SEQ + qb * 64)) * D3 + h * 64;
    #pragma unroll
    for (int i = t; i < 64 * 16; i += 256) {
        int r  = i >> 4;
        int cq = (i & 15) * 4;
        float4 v = *(const float4*)(qbase + (size_t)r * D3 + cq);
        Qs[r * 65 + cq + 0] = v.x;
        Qs[r * 65 + cq + 1] = v.y;
        Qs[r * 65 + cq + 2] = v.z;
        Qs[r * 65 + cq + 3] = v.w;
    }

    float m[4], l[4], o[4][4];
    #pragma unroll
    for (int i = 0; i < 4; i++) {
        m[i] = -1e30f; l[i] = 0.0f;
        #pragma unroll
        for (int j = 0; j < 4; j++) o[i][j] = 0.0f;
    }
    __syncthreads();

    for (int kt = 0; kt <= qb; kt++) {
        // Load K, V tiles
        const float* kb = qkv + ((size_t)(b * SEQ + kt * 64)) * D3 + DIM + h * 64;
        const float* vb = kb + DIM;
        for (int i = t; i < 64 * 16; i += 256) {
            int r  = i >> 4;
            int cq = (i & 15) * 4;
            float4 kv4 = *(const float4*)(kb + (size_t)r * D3 + cq);
            Ks[r * 65 + cq + 0] = kv4.x;
            Ks[r * 65 + cq + 1] = kv4.y;
            Ks[r * 65 + cq + 2] = kv4.z;
            Ks[r * 65 + cq + 3] = kv4.w;
            float4 vv = *(const float4*)(vb + (size_t)r * D3 + cq);
            *(float4*)&Vs[r * 64 + cq] = vv;
        }
        __syncthreads();

        // Scores: s[i][j] = sum_d Q[ty*4+i][d] * K[tx*4+j][d]
        float s[4][4];
        #pragma unroll
        for (int i = 0; i < 4; i++)
            #pragma unroll
            for (int j = 0; j < 4; j++) s[i][j] = 0.0f;

        #pragma unroll 16
        for (int d = 0; d < 64; d++) {
            float a0 = Qs[(ty * 4 + 0) * 65 + d];
            float a1 = Qs[(ty * 4 + 1) * 65 + d];
            float a2 = Qs[(ty * 4 + 2) * 65 + d];
            float a3 = Qs[(ty * 4 + 3) * 65 + d];
            float c0 = Ks[(tx * 4 + 0) * 65 + d];
            float c1 = Ks[(tx * 4 + 1) * 65 + d];
            float c2 = Ks[(tx * 4 + 2) * 65 + d];
            float c3 = Ks[(tx * 4 + 3) * 65 + d];
            s[0][0] += a0*c0; s[0][1] += a0*c1; s[0][2] += a0*c2; s[0][3] += a0*c3;
            s[1][0] += a1*c0; s[1][1] += a1*c1; s[1][2] += a1*c2; s[1][3] += a1*c3;
            s[2][0] += a2*c0; s[2][1] += a2*c1; s[2][2] += a2*c2; s[2][3] += a2*c3;
            s[3][0] += a3*c0; s[3][1] += a3*c1; s[3][2] += a3*c2; s[3][3] += a3*c3;
        }

        // Scale + causal mask
        int q0  = qb * 64 + ty * 4;
        int k0c = kt * 64 + tx * 4;
        #pragma unroll
        for (int i = 0; i < 4; i++)
            #pragma unroll
            for (int j = 0; j < 4; j++) {
                float v = s[i][j] * 0.125f;
                if (k0c + j > q0 + i) v = -1e30f;
                s[i][j] = v;
            }

        // Online softmax per query row (reduce across the 16 tx lanes)
        #pragma unroll
        for (int i = 0; i < 4; i++) {
            float mx = fmaxf(fmaxf(s[i][0], s[i][1]), fmaxf(s[i][2], s[i][3]));
            #pragma unroll
            for (int off = 1; off < 16; off <<= 1)
                mx = fmaxf(mx, __shfl_xor_sync(0xffffffffu, mx, off));
            float mn = fmaxf(m[i], mx);
            float p0 = __expf(s[i][0] - mn);
            float p1 = __expf(s[i][1] - mn);
            float p2 = __expf(s[i][2] - mn);
            float p3 = __expf(s[i][3] - mn);
            float rs = p0 + p1 + p2 + p3;
            #pragma unroll
            for (int off = 1; off < 16; off <<= 1)
                rs += __shfl_xor_sync(0xffffffffu, rs, off);
            float alpha = __expf(m[i] - mn);
            m[i] = mn;
            l[i] = l[i] * alpha + rs;
            #pragma unroll
            for (int j = 0; j < 4; j++) o[i][j] *= alpha;
            int pr = (ty * 4 + i) * 65 + tx * 4;
            Ps[pr + 0] = p0; Ps[pr + 1] = p1; Ps[pr + 2] = p2; Ps[pr + 3] = p3;
        }
        __syncthreads();

        // O += P @ V
        #pragma unroll 8
        for (int kv = 0; kv < 64; kv++) {
            float4 vv = *(const float4*)&Vs[kv * 64 + tx * 4];
            #pragma unroll
            for (int i = 0; i < 4; i++) {
                float p = Ps[(ty * 4 + i) * 65 + kv];
                o[i][0] += p * vv.x;
                o[i][1] += p * vv.y;
                o[i][2] += p * vv.z;
                o[i][3] += p * vv.w;
            }
        }
        __syncthreads();
    }

    // Write normalized output
    float* ob = out + ((size_t)(b * SEQ + qb * 64)) * DIM + h * 64;
    #pragma unroll
    for (int i = 0; i < 4; i++) {
        float inv = 1.0f / l[i];
        #pragma unroll
        for (int j = 0; j < 4; j++)
            ob[(size_t)(ty * 4 + i) * DIM + tx * 4 + j] = o[i][j] * inv;
    }
}

// ---------------------------------------------------------------------------
// Launch
// ---------------------------------------------------------------------------
extern "C" void kernel_launch(void* const* d_in, const int* in_sizes, int n_in,
                              void* d_out, int out_size)
{
    const float* x      = (const float*)d_in[0];
    const float* W_qkv  = (const float*)d_in[1];
    const float* b_qkv  = (const float*)d_in[2];
    const float* W_o    = (const float*)d_in[3];
    const float* b_o    = (const float*)d_in[4];
    const float* W_fc   = (const float*)d_in[5];
    const float* b_fc   = (const float*)d_in[6];
    const float* W_pr   = (const float*)d_in[7];
    const float* b_pr   = (const float*)d_in[8];
    const float* g1     = (const float*)d_in[9];
    const float* beta1  = (const float*)d_in[10];
    const float* g2     = (const float*)d_in[11];
    const float* beta2  = (const float*)d_in[12];
    float* out = (float*)d_out;

    float *p_h, *p_qkv, *p_att, *p_x1, *p_h2, *p_fc;
    cudaGetSymbolAddress((void**)&p_h,   g_h);
    cudaGetSymbolAddress((void**)&p_qkv, g_qkv);
    cudaGetSymbolAddress((void**)&p_att, g_att);
    cudaGetSymbolAddress((void**)&p_x1,  g_x1);
    cudaGetSymbolAddress((void**)&p_h2,  g_h2);
    cudaGetSymbolAddress((void**)&p_fc,  g_fc);

    cudaFuncSetAttribute(attn_kernel,
                         cudaFuncAttributeMaxDynamicSharedMemorySize, ATTN_SMEM);

    // 1. LN1
    ln_kernel<<<MROWS, 256>>>(x, g1, beta1, p_h);
    // 2. QKV projection: [4096,1024] @ [1024,3072]
    gemm128<0><<<dim3(3 * DIM / 128, MROWS / 128), 256>>>(
        p_h, W_qkv, b_qkv, nullptr, p_qkv, MROWS, 3 * DIM, DIM);
    // 3. Attention
    attn_kernel<<<dim3(SEQ / 64, BATCH * NHEAD), 256, ATTN_SMEM>>>(p_qkv, p_att);
    // 4. Output projection + residual
    gemm128<0><<<dim3(DIM / 128, MROWS / 128), 256>>>(
        p_att, W_o, b_o, x, p_x1, MROWS, DIM, DIM);
    // 5. LN2
    ln_kernel<<<MROWS, 256>>>(p_x1, g2, beta2, p_h2);
    // 6. FC + GELU: [4096,1024] @ [1024,4096]
    gemm128<1><<<dim3(4 * DIM / 128, MROWS / 128), 256>>>(
        p_h2, W_fc, b_fc, nullptr, p_fc, MROWS, 4 * DIM, DIM);
    // 7. Projection + residual -> out: [4096,4096] @ [4096,1024]
    gemm128<0><<<dim3(DIM / 128, MROWS / 128), 256>>>(
        p_fc, W_pr, b_pr, p_x1, out, MROWS, DIM, 4 * DIM);
}

// round 3
// speedup vs baseline: 1.7908x; 1.7908x over previous
#include <cuda_runtime.h>
#include <cuda_bf16.h>
#include <math.h>
#include <stdint.h>

// Problem constants
#define BATCH 2
#define SEQ   2048
#define DIM   1024
#define NHEAD 16
#define HDIM  64
#define MROWS (BATCH * SEQ)   // 4096

// ---------------------------------------------------------------------------
// Scratch (no allocations allowed -> __device__ globals)
// ---------------------------------------------------------------------------
__device__ __nv_bfloat16 g_Wqkv_h[3072 * 1024];
__device__ __nv_bfloat16 g_Wqkv_l[3072 * 1024];
__device__ __nv_bfloat16 g_Wo_h  [1024 * 1024];
__device__ __nv_bfloat16 g_Wo_l  [1024 * 1024];
__device__ __nv_bfloat16 g_Wfc_h [4096 * 1024];
__device__ __nv_bfloat16 g_Wfc_l [4096 * 1024];
__device__ __nv_bfloat16 g_Wpr_h [1024 * 4096];
__device__ __nv_bfloat16 g_Wpr_l [1024 * 4096];

__device__ __nv_bfloat16 g_h_h [MROWS * DIM];
__device__ __nv_bfloat16 g_h_l [MROWS * DIM];
__device__ float         g_qkv [MROWS * 3 * DIM];
__device__ float         g_att [MROWS * DIM];
__device__ __nv_bfloat16 g_att_h[MROWS * DIM];
__device__ __nv_bfloat16 g_att_l[MROWS * DIM];
__device__ float         g_x1  [MROWS * DIM];
__device__ __nv_bfloat16 g_h2_h[MROWS * DIM];
__device__ __nv_bfloat16 g_h2_l[MROWS * DIM];
__device__ __nv_bfloat16 g_fc_h[MROWS * 4 * DIM];
__device__ __nv_bfloat16 g_fc_l[MROWS * 4 * DIM];

// ---------------------------------------------------------------------------
// PTX helpers (family-common only: cp.async, ldmatrix, mma.sync)
// ---------------------------------------------------------------------------
__device__ __forceinline__ uint32_t smem_u32(const void* p) {
    uint32_t a;
    asm("{ .reg .u64 t; cvta.to.shared.u64 t, %1; cvt.u32.u64 %0, t; }"
        : "=r"(a) : "l"(p));
    return a;
}

__device__ __forceinline__ void cp16(uint32_t dst, const void* src) {
    asm volatile("cp.async.cg.shared.global [%0], [%1], 16;"
                 :: "r"(dst), "l"(src));
}
#define CP_COMMIT() asm volatile("cp.async.commit_group;" ::: "memory")
#define CP_WAIT1()  asm volatile("cp.async.wait_group 1;" ::: "memory")
#define CP_WAIT0()  asm volatile("cp.async.wait_group 0;" ::: "memory")

__device__ __forceinline__ void ldsm4(uint32_t* r, uint32_t a) {
    asm volatile("ldmatrix.sync.aligned.m8n8.x4.shared.b16 {%0,%1,%2,%3}, [%4];"
                 : "=r"(r[0]), "=r"(r[1]), "=r"(r[2]), "=r"(r[3]) : "r"(a));
}

__device__ __forceinline__ void mma16816(float* d, const uint32_t* a,
                                         uint32_t b0, uint32_t b1) {
    asm volatile(
        "mma.sync.aligned.m16n8k16.row.col.f32.bf16.bf16.f32 "
        "{%0,%1,%2,%3}, {%4,%5,%6,%7}, {%8,%9}, {%0,%1,%2,%3};"
        : "+f"(d[0]), "+f"(d[1]), "+f"(d[2]), "+f"(d[3])
        : "r"(a[0]), "r"(a[1]), "r"(a[2]), "r"(a[3]), "r"(b0), "r"(b1));
}

// ---------------------------------------------------------------------------
// bf16 mma.sync GEMM with hi/lo 3-term compensation.
// C[M,N] = epi(sum_k A[m,k]*Bt[n,k]), A hi/lo [M,K] K-major, Bt hi/lo [N,K].
// Block tile 128x128x32, 8 warps (2x4), warp tile 64x32.
// EPI: 0 = +bias -> fp32; 1 = +bias+res -> fp32; 2 = gelu(+bias) -> bf16 hi/lo
// ---------------------------------------------------------------------------
#define TS 40                       // smem row stride in bf16 elems (80 bytes)
#define TILE_B (128 * TS * 2)       // 10240 bytes per tile
#define STAGE_B (4 * TILE_B)        // 40960 bytes per stage (Ah,Al,Bh,Bl)
#define GEMM_SMEM (2 * STAGE_B)     // 81920

template <int EPI>
__global__ __launch_bounds__(256) void gemm_mma(
    const __nv_bfloat16* __restrict__ Ah, const __nv_bfloat16* __restrict__ Al,
    const __nv_bfloat16* __restrict__ Bh, const __nv_bfloat16* __restrict__ Bl,
    const float* __restrict__ bias, const float* __restrict__ res,
    float* __restrict__ Co, __nv_bfloat16* __restrict__ Ch,
    __nv_bfloat16* __restrict__ Cl, int M, int N, int K)
{
    extern __shared__ char sm_raw[];
    uint32_t sb = smem_u32(sm_raw);

    int tid  = threadIdx.x;
    int w    = tid >> 5;
    int lane = tid & 31;
    int wm   = w >> 2;               // 0..1
    int wn   = w & 3;                // 0..3
    int n0   = blockIdx.x * 128;
    int m0   = blockIdx.y * 128;

    const __nv_bfloat16* srcs[4] = {
        Ah + (size_t)m0 * K, Al + (size_t)m0 * K,
        Bh + (size_t)n0 * K, Bl + (size_t)n0 * K };

    // per-thread load decode (8 x 16B chunks per stage)
    int l_chunk = tid & 3;
    int l_row   = (tid >> 2) & 63;   // rows via 2 iters of 64? -> use idx decode below

    float acc[4][4][4];
    #pragma unroll
    for (int i = 0; i < 4; i++)
        #pragma unroll
        for (int j = 0; j < 4; j++)
            #pragma unroll
            for (int q = 0; q < 4; q++) acc[i][j][q] = 0.0f;

    int nch = K >> 5;                // K/32

    // stage loader: 4 tiles x 128 rows x 4 chunks(16B) = 2048 cp / 256 thr = 8
    auto load_stage = [&](int c, int s) {
        int k0 = c << 5;
        uint32_t stg = sb + s * STAGE_B;
        #pragma unroll
        for (int it = 0; it < 8; it++) {
            int idx   = it * 256 + tid;
            int chunk = idx & 3;
            int row   = (idx >> 2) & 127;
            int t     = idx >> 9;          // 0..3
            const __nv_bfloat16* src = srcs[t] + (size_t)row * K + k0 + chunk * 8;
            uint32_t dst = stg + t * TILE_B + (uint32_t)(row * TS + chunk * 8) * 2;
            cp16(dst, src);
        }
        CP_COMMIT();
    };

    load_stage(0, 0);
    load_stage(1, 1);

    // fragment smem offsets (bytes), within a stage
    int arow = wm * 64 + (lane & 15);
    uint32_t a_off = (uint32_t)(arow * TS + (lane >> 4) * 8) * 2;
    int bmat = lane >> 3;                 // 0..3
    int b_h  = bmat & 1;
    int b_j  = bmat >> 1;
    int brow = wn * 32 + (lane & 7);
    uint32_t b_off0 = (uint32_t)((brow + b_j * 8) * TS + b_h * 8) * 2;       // jj=0
    uint32_t b_off2 = (uint32_t)((brow + (b_j + 2) * 8) * TS + b_h * 8) * 2; // jj=2

    for (int c = 0; c < nch; c++) {
        int s = c & 1;
        if (c + 1 < nch) { CP_WAIT1(); } else { CP_WAIT0(); }
        __syncthreads();

        uint32_t stg = sb + s * STAGE_B;
        uint32_t pAh = stg;
        uint32_t pAl = stg + TILE_B;
        uint32_t pBh = stg + 2 * TILE_B;
        uint32_t pBl = stg + 3 * TILE_B;

        #pragma unroll
        for (int kk = 0; kk < 32; kk += 16) {
            uint32_t kb = (uint32_t)kk * 2;
            uint32_t ah[4][4], al[4][4];
            #pragma unroll
            for (int i = 0; i < 4; i++) {
                ldsm4(ah[i], pAh + a_off + kb + (uint32_t)i * 16 * TS * 2);
                ldsm4(al[i], pAl + a_off + kb + (uint32_t)i * 16 * TS * 2);
            }
            #pragma unroll
            for (int jj = 0; jj < 4; jj += 2) {
                uint32_t boff = (jj == 0) ? b_off0 : b_off2;
                uint32_t bh[4], bl[4];
                ldsm4(bh, pBh + boff + kb);
                ldsm4(bl, pBl + boff + kb);
                #pragma unroll
                for (int i = 0; i < 4; i++) {
                    mma16816(acc[i][jj],     ah[i], bh[0], bh[1]);
                    mma16816(acc[i][jj + 1], ah[i], bh[2], bh[3]);
                    mma16816(acc[i][jj],     ah[i], bl[0], bl[1]);
                    mma16816(acc[i][jj + 1], ah[i], bl[2], bl[3]);
                    mma16816(acc[i][jj],     al[i], bh[0], bh[1]);
                    mma16816(acc[i][jj + 1], al[i], bh[2], bh[3]);
                }
            }
        }
        __syncthreads();
        if (c + 2 < nch) load_stage(c + 2, s);
    }

    // Epilogue: mma accum layout -> global
    int r0 = m0 + wm * 64 + (lane >> 2);
    int c0 = n0 + wn * 32 + (lane & 3) * 2;
    #pragma unroll
    for (int i = 0; i < 4; i++) {
        int row = r0 + i * 16;
        #pragma unroll
        for (int j = 0; j < 4; j++) {
            int col = c0 + j * 8;
            float b0 = bias[col], b1 = bias[col + 1];
            float v0 = acc[i][j][0] + b0;
            float v1 = acc[i][j][1] + b1;
            float v2 = acc[i][j][2] + b0;
            float v3 = acc[i][j][3] + b1;
            if (EPI == 1) {
                const float* rp0 = res + (size_t)row * N + col;
                const float* rp1 = res + (size_t)(row + 8) * N + col;
                v0 += rp0[0]; v1 += rp0[1];
                v2 += rp1[0]; v3 += rp1[1];
            }
            if (EPI == 2) {
                v0 = 0.5f * v0 * (1.0f + erff(v0 * 0.70710678118654752f));
                v1 = 0.5f * v1 * (1.0f + erff(v1 * 0.70710678118654752f));
                v2 = 0.5f * v2 * (1.0f + erff(v2 * 0.70710678118654752f));
                v3 = 0.5f * v3 * (1.0f + erff(v3 * 0.70710678118654752f));
                __nv_bfloat16 h0 = __float2bfloat16(v0);
                __nv_bfloat16 h1 = __float2bfloat16(v1);
                __nv_bfloat16 h2 = __float2bfloat16(v2);
                __nv_bfloat16 h3 = __float2bfloat16(v3);
                *(__nv_bfloat162*)(Ch + (size_t)row * N + col) = __nv_bfloat162(h0, h1);
                *(__nv_bfloat162*)(Ch + (size_t)(row + 8) * N + col) = __nv_bfloat162(h2, h3);
                *(__nv_bfloat162*)(Cl + (size_t)row * N + col) =
                    __nv_bfloat162(__float2bfloat16(v0 - __bfloat162float(h0)),
                                   __float2bfloat16(v1 - __bfloat162float(h1)));
                *(__nv_bfloat162*)(Cl + (size_t)(row + 8) * N + col) =
                    __nv_bfloat162(__float2bfloat16(v2 - __bfloat162float(h2)),
                                   __float2bfloat16(v3 - __bfloat162float(h3)));
            } else {
                *(float2*)(Co + (size_t)row * N + col) = make_float2(v0, v1);
                *(float2*)(Co + (size_t)(row + 8) * N + col) = make_float2(v2, v3);
            }
        }
    }
}

// ---------------------------------------------------------------------------
// Weight prep: W[K,N] fp32 -> Wt hi/lo bf16 [N,K]
// ---------------------------------------------------------------------------
__global__ __launch_bounds__(256) void wtrans_kernel(
    const float* __restrict__ W, __nv_bfloat16* __restrict__ Th,
    __nv_bfloat16* __restrict__ Tl, int K, int N)
{
    __shared__ float t[32][33];
    int n0 = blockIdx.x * 32, k0 = blockIdx.y * 32;
    int tx = threadIdx.x & 31, ty = threadIdx.x >> 5;  // ty 0..7
    #pragma unroll
    for (int i = 0; i < 4; i++) {
        int kr = ty * 4 + i;
        t[kr][tx] = W[(size_t)(k0 + kr) * N + n0 + tx];
    }
    __syncthreads();
    #pragma unroll
    for (int i = 0; i < 4; i++) {
        int nr = ty * 4 + i;
        float v = t[tx][nr];
        size_t o = (size_t)(n0 + nr) * K + k0 + tx;
        __nv_bfloat16 hv = __float2bfloat16(v);
        Th[o] = hv;
        Tl[o] = __float2bfloat16(v - __bfloat162float(hv));
    }
}

// ---------------------------------------------------------------------------
// fp32 -> bf16 hi/lo split (no transpose)
// ---------------------------------------------------------------------------
__global__ __launch_bounds__(256) void split_kernel(
    const float* __restrict__ x, __nv_bfloat16* __restrict__ h,
    __nv_bfloat16* __restrict__ l, int n4)
{
    int i = blockIdx.x * 256 + threadIdx.x;
    if (i >= n4) return;
    float4 v = ((const float4*)x)[i];
    __nv_bfloat16 h0 = __float2bfloat16(v.x);
    __nv_bfloat16 h1 = __float2bfloat16(v.y);
    __nv_bfloat16 h2 = __float2bfloat16(v.z);
    __nv_bfloat16 h3 = __float2bfloat16(v.w);
    __nv_bfloat162* hp = (__nv_bfloat162*)(h + (size_t)i * 4);
    hp[0] = __nv_bfloat162(h0, h1);
    hp[1] = __nv_bfloat162(h2, h3);
    __nv_bfloat162* lp = (__nv_bfloat162*)(l + (size_t)i * 4);
    lp[0] = __nv_bfloat162(__float2bfloat16(v.x - __bfloat162float(h0)),
                           __float2bfloat16(v.y - __bfloat162float(h1)));
    lp[1] = __nv_bfloat162(__float2bfloat16(v.z - __bfloat162float(h2)),
                           __float2bfloat16(v.w - __bfloat162float(h3)));
}

// ---------------------------------------------------------------------------
// LayerNorm -> bf16 hi/lo outputs. One block per row, 256 threads, float4.
// ---------------------------------------------------------------------------
__global__ __launch_bounds__(256) void ln_kernel(
    const float* __restrict__ x, const float* __restrict__ g,
    const float* __restrict__ b, __nv_bfloat16* __restrict__ yh,
    __nv_bfloat16* __restrict__ yl)
{
    __shared__ float sh[16];
    int row = blockIdx.x;
    int t = threadIdx.x;
    const float4* xr = (const float4*)(x + (size_t)row * DIM);
    float4 v = xr[t];
    float s  = v.x + v.y + v.z + v.w;
    float s2 = v.x*v.x + v.y*v.y + v.z*v.z + v.w*v.w;
    #pragma unroll
    for (int o = 16; o > 0; o >>= 1) {
        s  += __shfl_xor_sync(0xffffffffu, s,  o);
        s2 += __shfl_xor_sync(0xffffffffu, s2, o);
    }
    if ((t & 31) == 0) { sh[t >> 5] = s; sh[8 + (t >> 5)] = s2; }
    __syncthreads();
    if (t < 32) {
        float a  = (t < 8) ? sh[t]     : 0.0f;
        float a2 = (t < 8) ? sh[8 + t] : 0.0f;
        #pragma unroll
        for (int o = 4; o > 0; o >>= 1) {
            a  += __shfl_xor_sync(0xffffffffu, a,  o);
            a2 += __shfl_xor_sync(0xffffffffu, a2, o);
        }
        if (t == 0) { sh[0] = a; sh[1] = a2; }
    }
    __syncthreads();
    float mean = sh[0] * (1.0f / DIM);
    float var  = sh[1] * (1.0f / DIM) - mean * mean;
    float rstd = rsqrtf(var + 1e-5f);
    float4 gg = ((const float4*)g)[t];
    float4 bb = ((const float4*)b)[t];
    float o0 = (v.x - mean) * rstd * gg.x + bb.x;
    float o1 = (v.y - mean) * rstd * gg.y + bb.y;
    float o2 = (v.z - mean) * rstd * gg.z + bb.z;
    float o3 = (v.w - mean) * rstd * gg.w + bb.w;
    __nv_bfloat16 h0 = __float2bfloat16(o0);
    __nv_bfloat16 h1 = __float2bfloat16(o1);
    __nv_bfloat16 h2 = __float2bfloat16(o2);
    __nv_bfloat16 h3 = __float2bfloat16(o3);
    size_t o = (size_t)row * DIM + t * 4;
    __nv_bfloat162* hp = (__nv_bfloat162*)(yh + o);
    hp[0] = __nv_bfloat162(h0, h1);
    hp[1] = __nv_bfloat162(h2, h3);
    __nv_bfloat162* lp = (__nv_bfloat162*)(yl + o);
    lp[0] = __nv_bfloat162(__float2bfloat16(o0 - __bfloat162float(h0)),
                           __float2bfloat16(o1 - __bfloat162float(h1)));
    lp[1] = __nv_bfloat162(__float2bfloat16(o2 - __bfloat162float(h2)),
                           __float2bfloat16(o3 - __bfloat162float(h3)));
}

// ---------------------------------------------------------------------------
// Flash attention, fp32 (unchanged from passing baseline).
// ---------------------------------------------------------------------------
#define ATTN_SMEM ((3 * 64 * 65 + 64 * 64) * 4)

__global__ __launch_bounds__(256) void attn_kernel(
    const float* __restrict__ qkv, float* __restrict__ out)
{
    extern __shared__ float sm[];
    float* Qs = sm;
    float* Ks = Qs + 64 * 65;
    float* Ps = Ks + 64 * 65;
    float* Vs = Ps + 64 * 65;

    const int D3 = 3 * DIM;
    int qb = blockIdx.x;
    int bh = blockIdx.y;
    int b  = bh >> 4;
    int h  = bh & 15;
    int t  = threadIdx.x;
    int ty = t >> 4;
    int tx = t & 15;

    const float* qbase = qkv + ((size_t)(b * SEQ + qb * 64)) * D3 + h * 64;
    #pragma unroll
    for (int i = t; i < 64 * 16; i += 256) {
        int r  = i >> 4;
        int cq = (i & 15) * 4;
        float4 v = *(const float4*)(qbase + (size_t)r * D3 + cq);
        Qs[r * 65 + cq + 0] = v.x;
        Qs[r * 65 + cq + 1] = v.y;
        Qs[r * 65 + cq + 2] = v.z;
        Qs[r * 65 + cq + 3] = v.w;
    }

    float m[4], l[4], o[4][4];
    #pragma unroll
    for (int i = 0; i < 4; i++) {
        m[i] = -1e30f; l[i] = 0.0f;
        #pragma unroll
        for (int j = 0; j < 4; j++) o[i][j] = 0.0f;
    }
    __syncthreads();

    for (int kt = 0; kt <= qb; kt++) {
        const float* kb = qkv + ((size_t)(b * SEQ + kt * 64)) * D3 + DIM + h * 64;
        const float* vb = kb + DIM;
        for (int i = t; i < 64 * 16; i += 256) {
            int r  = i >> 4;
            int cq = (i & 15) * 4;
            float4 kv4 = *(const float4*)(kb + (size_t)r * D3 + cq);
            Ks[r * 65 + cq + 0] = kv4.x;
            Ks[r * 65 + cq + 1] = kv4.y;
            Ks[r * 65 + cq + 2] = kv4.z;
            Ks[r * 65 + cq + 3] = kv4.w;
            float4 vv = *(const float4*)(vb + (size_t)r * D3 + cq);
            *(float4*)&Vs[r * 64 + cq] = vv;
        }
        __syncthreads();

        float s[4][4];
        #pragma unroll
        for (int i = 0; i < 4; i++)
            #pragma unroll
            for (int j = 0; j < 4; j++) s[i][j] = 0.0f;

        #pragma unroll 16
        for (int d = 0; d < 64; d++) {
            float a0 = Qs[(ty * 4 + 0) * 65 + d];
            float a1 = Qs[(ty * 4 + 1) * 65 + d];
            float a2 = Qs[(ty * 4 + 2) * 65 + d];
            float a3 = Qs[(ty * 4 + 3) * 65 + d];
            float c0 = Ks[(tx * 4 + 0) * 65 + d];
            float c1 = Ks[(tx * 4 + 1) * 65 + d];
            float c2 = Ks[(tx * 4 + 2) * 65 + d];
            float c3 = Ks[(tx * 4 + 3) * 65 + d];
            s[0][0] += a0*c0; s[0][1] += a0*c1; s[0][2] += a0*c2; s[0][3] += a0*c3;
            s[1][0] += a1*c0; s[1][1] += a1*c1; s[1][2] += a1*c2; s[1][3] += a1*c3;
            s[2][0] += a2*c0; s[2][1] += a2*c1; s[2][2] += a2*c2; s[2][3] += a2*c3;
            s[3][0] += a3*c0; s[3][1] += a3*c1; s[3][2] += a3*c2; s[3][3] += a3*c3;
        }

        int q0  = qb * 64 + ty * 4;
        int k0c = kt * 64 + tx * 4;
        #pragma unroll
        for (int i = 0; i < 4; i++)
            #pragma unroll
            for (int j = 0; j < 4; j++) {
                float v = s[i][j] * 0.125f;
                if (k0c + j > q0 + i) v = -1e30f;
                s[i][j] = v;
            }

        #pragma unroll
        for (int i = 0; i < 4; i++) {
            float mx = fmaxf(fmaxf(s[i][0], s[i][1]), fmaxf(s[i][2], s[i][3]));
            #pragma unroll
            for (int off = 1; off < 16; off <<= 1)
                mx = fmaxf(mx, __shfl_xor_sync(0xffffffffu, mx, off));
            float mn = fmaxf(m[i], mx);
            float p0 = __expf(s[i][0] - mn);
            float p1 = __expf(s[i][1] - mn);
            float p2 = __expf(s[i][2] - mn);
            float p3 = __expf(s[i][3] - mn);
            float rs = p0 + p1 + p2 + p3;
            #pragma unroll
            for (int off = 1; off < 16; off <<= 1)
                rs += __shfl_xor_sync(0xffffffffu, rs, off);
            float alpha = __expf(m[i] - mn);
            m[i] = mn;
            l[i] = l[i] * alpha + rs;
            #pragma unroll
            for (int j = 0; j < 4; j++) o[i][j] *= alpha;
            int pr = (ty * 4 + i) * 65 + tx * 4;
            Ps[pr + 0] = p0; Ps[pr + 1] = p1; Ps[pr + 2] = p2; Ps[pr + 3] = p3;
        }
        __syncthreads();

        #pragma unroll 8
        for (int kv = 0; kv < 64; kv++) {
            float4 vv = *(const float4*)&Vs[kv * 64 + tx * 4];
            #pragma unroll
            for (int i = 0; i < 4; i++) {
                float p = Ps[(ty * 4 + i) * 65 + kv];
                o[i][0] += p * vv.x;
                o[i][1] += p * vv.y;
                o[i][2] += p * vv.z;
                o[i][3] += p * vv.w;
            }
        }
        __syncthreads();
    }

    float* ob = out + ((size_t)(b * SEQ + qb * 64)) * DIM + h * 64;
    #pragma unroll
    for (int i = 0; i < 4; i++) {
        float inv = 1.0f / l[i];
        #pragma unroll
        for (int j = 0; j < 4; j++)
            ob[(size_t)(ty * 4 + i) * DIM + tx * 4 + j] = o[i][j] * inv;
    }
}

// ---------------------------------------------------------------------------
// Launch
// ---------------------------------------------------------------------------
extern "C" void kernel_launch(void* const* d_in, const int* in_sizes, int n_in,
                              void* d_out, int out_size)
{
    const float* x      = (const float*)d_in[0];
    const float* W_qkv  = (const float*)d_in[1];
    const float* b_qkv  = (const float*)d_in[2];
    const float* W_o    = (const float*)d_in[3];
    const float* b_o    = (const float*)d_in[4];
    const float* W_fc   = (const float*)d_in[5];
    const float* b_fc   = (const float*)d_in[6];
    const float* W_pr   = (const float*)d_in[7];
    const float* b_pr   = (const float*)d_in[8];
    const float* g1     = (const float*)d_in[9];
    const float* beta1  = (const float*)d_in[10];
    const float* g2     = (const float*)d_in[11];
    const float* beta2  = (const float*)d_in[12];
    float* out = (float*)d_out;

    __nv_bfloat16 *pWqh, *pWql, *pWoh, *pWol, *pWfh, *pWfl, *pWph, *pWpl;
    __nv_bfloat16 *phh, *phl, *path, *patl, *ph2h, *ph2l, *pfch, *pfcl;
    float *pqkv, *patt, *px1;
    cudaGetSymbolAddress((void**)&pWqh, g_Wqkv_h);
    cudaGetSymbolAddress((void**)&pWql, g_Wqkv_l);
    cudaGetSymbolAddress((void**)&pWoh, g_Wo_h);
    cudaGetSymbolAddress((void**)&pWol, g_Wo_l);
    cudaGetSymbolAddress((void**)&pWfh, g_Wfc_h);
    cudaGetSymbolAddress((void**)&pWfl, g_Wfc_l);
    cudaGetSymbolAddress((void**)&pWph, g_Wpr_h);
    cudaGetSymbolAddress((void**)&pWpl, g_Wpr_l);
    cudaGetSymbolAddress((void**)&phh,  g_h_h);
    cudaGetSymbolAddress((void**)&phl,  g_h_l);
    cudaGetSymbolAddress((void**)&pqkv, g_qkv);
    cudaGetSymbolAddress((void**)&patt, g_att);
    cudaGetSymbolAddress((void**)&path, g_att_h);
    cudaGetSymbolAddress((void**)&patl, g_att_l);
    cudaGetSymbolAddress((void**)&px1,  g_x1);
    cudaGetSymbolAddress((void**)&ph2h, g_h2_h);
    cudaGetSymbolAddress((void**)&ph2l, g_h2_l);
    cudaGetSymbolAddress((void**)&pfch, g_fc_h);
    cudaGetSymbolAddress((void**)&pfcl, g_fc_l);

    cudaFuncSetAttribute(attn_kernel,
                         cudaFuncAttributeMaxDynamicSharedMemorySize, ATTN_SMEM);
    cudaFuncSetAttribute(gemm_mma<0>,
                         cudaFuncAttributeMaxDynamicSharedMemorySize, GEMM_SMEM);
    cudaFuncSetAttribute(gemm_mma<1>,
                         cudaFuncAttributeMaxDynamicSharedMemorySize, GEMM_SMEM);
    cudaFuncSetAttribute(gemm_mma<2>,
                         cudaFuncAttributeMaxDynamicSharedMemorySize, GEMM_SMEM);

    // Weight prep (transpose + hi/lo split)
    wtrans_kernel<<<dim3(3072 / 32, 1024 / 32), 256>>>(W_qkv, pWqh, pWql, 1024, 3072);
    wtrans_kernel<<<dim3(1024 / 32, 1024 / 32), 256>>>(W_o,   pWoh, pWol, 1024, 1024);
    wtrans_kernel<<<dim3(4096 / 32, 1024 / 32), 256>>>(W_fc,  pWfh, pWfl, 1024, 4096);
    wtrans_kernel<<<dim3(1024 / 32, 4096 / 32), 256>>>(W_pr,  pWph, pWpl, 4096, 1024);

    // 1. LN1 -> h (hi/lo)
    ln_kernel<<<MROWS, 256>>>(x, g1, beta1, phh, phl);
    // 2. QKV projection: [4096,1024] @ [1024,3072]
    gemm_mma<0><<<dim3(3072 / 128, MROWS / 128), 256, GEMM_SMEM>>>(
        phh, phl, pWqh, pWql, b_qkv, nullptr, pqkv, nullptr, nullptr,
        MROWS, 3 * DIM, DIM);
    // 3. Attention
    attn_kernel<<<dim3(SEQ / 64, BATCH * NHEAD), 256, ATTN_SMEM>>>(pqkv, patt);
    // 3b. Split attention output
    split_kernel<<<(MROWS * DIM / 4 + 255) / 256, 256>>>(patt, path, patl, MROWS * DIM / 4);
    // 4. Output projection + residual -> x1
    gemm_mma<1><<<dim3(DIM / 128, MROWS / 128), 256, GEMM_SMEM>>>(
        path, patl, pWoh, pWol, b_o, x, px1, nullptr, nullptr,
        MROWS, DIM, DIM);
    // 5. LN2 -> h2 (hi/lo)
    ln_kernel<<<MROWS, 256>>>(px1, g2, beta2, ph2h, ph2l);
    // 6. FC + GELU -> fc (hi/lo)
    gemm_mma<2><<<dim3(4 * DIM / 128, MROWS / 128), 256, GEMM_SMEM>>>(
        ph2h, ph2l, pWfh, pWfl, b_fc, nullptr, nullptr, pfch, pfcl,
        MROWS, 4 * DIM, DIM);
    // 7. Projection + residual -> out
    gemm_mma<1><<<dim3(DIM / 128, MROWS / 128), 256, GEMM_SMEM>>>(
        pfch, pfcl, pWph, pWpl, b_pr, px1, out, nullptr, nullptr,
        MROWS, DIM, 4 * DIM);
}

// round 4
// speedup vs baseline: 2.2979x; 1.2832x over previous
#include <cuda_runtime.h>
#include <cuda_bf16.h>
#include <math.h>
#include <stdint.h>
#include <string.h>

// Problem constants
#define BATCH 2
#define SEQ   2048
#define DIM   1024
#define NHEAD 16
#define HDIM  64
#define MROWS (BATCH * SEQ)   // 4096

// ---------------------------------------------------------------------------
// Scratch (no allocations allowed -> __device__ globals)
// ---------------------------------------------------------------------------
__device__ __nv_bfloat16 g_Wqkv_h[3072 * 1024];
__device__ __nv_bfloat16 g_Wqkv_l[3072 * 1024];
__device__ __nv_bfloat16 g_Wo_h  [1024 * 1024];
__device__ __nv_bfloat16 g_Wo_l  [1024 * 1024];
__device__ __nv_bfloat16 g_Wfc_h [4096 * 1024];
__device__ __nv_bfloat16 g_Wfc_l [4096 * 1024];
__device__ __nv_bfloat16 g_Wpr_h [1024 * 4096];
__device__ __nv_bfloat16 g_Wpr_l [1024 * 4096];

__device__ __nv_bfloat16 g_h_h [MROWS * DIM];
__device__ __nv_bfloat16 g_h_l [MROWS * DIM];
__device__ __nv_bfloat16 g_qkv_h[MROWS * 3 * DIM];
__device__ __nv_bfloat16 g_qkv_l[MROWS * 3 * DIM];
__device__ __nv_bfloat16 g_att_h[MROWS * DIM];
__device__ __nv_bfloat16 g_att_l[MROWS * DIM];
__device__ float         g_x1  [MROWS * DIM];
__device__ __nv_bfloat16 g_h2_h[MROWS * DIM];
__device__ __nv_bfloat16 g_h2_l[MROWS * DIM];
__device__ __nv_bfloat16 g_fc_h[MROWS * 4 * DIM];
__device__ __nv_bfloat16 g_fc_l[MROWS * 4 * DIM];

// ---------------------------------------------------------------------------
// PTX helpers (family-common only: cp.async, ldmatrix, mma.sync)
// ---------------------------------------------------------------------------
__device__ __forceinline__ uint32_t smem_u32(const void* p) {
    uint32_t a;
    asm("{ .reg .u64 t; cvta.to.shared.u64 t, %1; cvt.u32.u64 %0, t; }"
        : "=r"(a) : "l"(p));
    return a;
}

__device__ __forceinline__ void cp16(uint32_t dst, const void* src) {
    asm volatile("cp.async.cg.shared.global [%0], [%1], 16;"
                 :: "r"(dst), "l"(src));
}
#define CP_COMMIT() asm volatile("cp.async.commit_group;" ::: "memory")
#define CP_WAIT1()  asm volatile("cp.async.wait_group 1;" ::: "memory")
#define CP_WAIT0()  asm volatile("cp.async.wait_group 0;" ::: "memory")

__device__ __forceinline__ void ldsm4(uint32_t* r, uint32_t a) {
    asm volatile("ldmatrix.sync.aligned.m8n8.x4.shared.b16 {%0,%1,%2,%3}, [%4];"
                 : "=r"(r[0]), "=r"(r[1]), "=r"(r[2]), "=r"(r[3]) : "r"(a));
}
__device__ __forceinline__ void ldsm4t(uint32_t* r, uint32_t a) {
    asm volatile("ldmatrix.sync.aligned.m8n8.x4.trans.shared.b16 {%0,%1,%2,%3}, [%4];"
                 : "=r"(r[0]), "=r"(r[1]), "=r"(r[2]), "=r"(r[3]) : "r"(a));
}

__device__ __forceinline__ void mma16816(float* d, const uint32_t* a,
                                         uint32_t b0, uint32_t b1) {
    asm volatile(
        "mma.sync.aligned.m16n8k16.row.col.f32.bf16.bf16.f32 "
        "{%0,%1,%2,%3}, {%4,%5,%6,%7}, {%8,%9}, {%0,%1,%2,%3};"
        : "+f"(d[0]), "+f"(d[1]), "+f"(d[2]), "+f"(d[3])
        : "r"(a[0]), "r"(a[1]), "r"(a[2]), "r"(a[3]), "r"(b0), "r"(b1));
}

__device__ __forceinline__ uint32_t pk2(__nv_bfloat16 a, __nv_bfloat16 b) {
    __nv_bfloat162 t(a, b);
    uint32_t r;
    memcpy(&r, &t, 4);
    return r;
}

// ---------------------------------------------------------------------------
// bf16 mma.sync GEMM with hi/lo 3-term compensation.
// C[M,N] = epi(sum_k A[m,k]*Bt[n,k]), A hi/lo [M,K] K-major, Bt hi/lo [N,K].
// Block tile 128x128x32, 8 warps (2x4), warp tile 64x32.
// EPI: 0 = +bias -> fp32; 1 = +bias+res -> fp32; 2 = gelu(+bias) -> bf16 hi/lo
//      3 = +bias -> bf16 hi/lo
// ---------------------------------------------------------------------------
#define TS 40                       // smem row stride in bf16 elems (80 bytes)
#define TILE_B (128 * TS * 2)       // 10240 bytes per tile
#define STAGE_B (4 * TILE_B)        // 40960 bytes per stage (Ah,Al,Bh,Bl)
#define GEMM_SMEM (2 * STAGE_B)     // 81920

template <int EPI>
__global__ __launch_bounds__(256) void gemm_mma(
    const __nv_bfloat16* __restrict__ Ah, const __nv_bfloat16* __restrict__ Al,
    const __nv_bfloat16* __restrict__ Bh, const __nv_bfloat16* __restrict__ Bl,
    const float* __restrict__ bias, const float* __restrict__ res,
    float* __restrict__ Co, __nv_bfloat16* __restrict__ Ch,
    __nv_bfloat16* __restrict__ Cl, int M, int N, int K)
{
    extern __shared__ char sm_raw[];
    uint32_t sb = smem_u32(sm_raw);

    int tid  = threadIdx.x;
    int w    = tid >> 5;
    int lane = tid & 31;
    int wm   = w >> 2;               // 0..1
    int wn   = w & 3;                // 0..3
    int n0   = blockIdx.x * 128;
    int m0   = blockIdx.y * 128;

    const __nv_bfloat16* srcs[4] = {
        Ah + (size_t)m0 * K, Al + (size_t)m0 * K,
        Bh + (size_t)n0 * K, Bl + (size_t)n0 * K };

    float acc[4][4][4];
    #pragma unroll
    for (int i = 0; i < 4; i++)
        #pragma unroll
        for (int j = 0; j < 4; j++)
            #pragma unroll
            for (int q = 0; q < 4; q++) acc[i][j][q] = 0.0f;

    int nch = K >> 5;                // K/32

    auto load_stage = [&](int c, int s) {
        int k0 = c << 5;
        uint32_t stg = sb + s * STAGE_B;
        #pragma unroll
        for (int it = 0; it < 8; it++) {
            int idx   = it * 256 + tid;
            int chunk = idx & 3;
            int row   = (idx >> 2) & 127;
            int t     = idx >> 9;          // 0..3
            const __nv_bfloat16* src = srcs[t] + (size_t)row * K + k0 + chunk * 8;
            uint32_t dst = stg + t * TILE_B + (uint32_t)(row * TS + chunk * 8) * 2;
            cp16(dst, src);
        }
        CP_COMMIT();
    };

    load_stage(0, 0);
    load_stage(1, 1);

    int arow = wm * 64 + (lane & 15);
    uint32_t a_off = (uint32_t)(arow * TS + (lane >> 4) * 8) * 2;
    int bmat = lane >> 3;                 // 0..3
    int b_h  = bmat & 1;
    int b_j  = bmat >> 1;
    int brow = wn * 32 + (lane & 7);
    uint32_t b_off0 = (uint32_t)((brow + b_j * 8) * TS + b_h * 8) * 2;
    uint32_t b_off2 = (uint32_t)((brow + (b_j + 2) * 8) * TS + b_h * 8) * 2;

    for (int c = 0; c < nch; c++) {
        int s = c & 1;
        if (c + 1 < nch) { CP_WAIT1(); } else { CP_WAIT0(); }
        __syncthreads();

        uint32_t stg = sb + s * STAGE_B;
        uint32_t pAh = stg;
        uint32_t pAl = stg + TILE_B;
        uint32_t pBh = stg + 2 * TILE_B;
        uint32_t pBl = stg + 3 * TILE_B;

        #pragma unroll
        for (int kk = 0; kk < 32; kk += 16) {
            uint32_t kb = (uint32_t)kk * 2;
            uint32_t ah[4][4], al[4][4];
            #pragma unroll
            for (int i = 0; i < 4; i++) {
                ldsm4(ah[i], pAh + a_off + kb + (uint32_t)i * 16 * TS * 2);
                ldsm4(al[i], pAl + a_off + kb + (uint32_t)i * 16 * TS * 2);
            }
            #pragma unroll
            for (int jj = 0; jj < 4; jj += 2) {
                uint32_t boff = (jj == 0) ? b_off0 : b_off2;
                uint32_t bh[4], bl[4];
                ldsm4(bh, pBh + boff + kb);
                ldsm4(bl, pBl + boff + kb);
                #pragma unroll
                for (int i = 0; i < 4; i++) {
                    mma16816(acc[i][jj],     ah[i], bh[0], bh[1]);
                    mma16816(acc[i][jj + 1], ah[i], bh[2], bh[3]);
                    mma16816(acc[i][jj],     ah[i], bl[0], bl[1]);
                    mma16816(acc[i][jj + 1], ah[i], bl[2], bl[3]);
                    mma16816(acc[i][jj],     al[i], bh[0], bh[1]);
                    mma16816(acc[i][jj + 1], al[i], bh[2], bh[3]);
                }
            }
        }
        __syncthreads();
        if (c + 2 < nch) load_stage(c + 2, s);
    }

    // Epilogue
    int r0 = m0 + wm * 64 + (lane >> 2);
    int c0 = n0 + wn * 32 + (lane & 3) * 2;
    #pragma unroll
    for (int i = 0; i < 4; i++) {
        int row = r0 + i * 16;
        #pragma unroll
        for (int j = 0; j < 4; j++) {
            int col = c0 + j * 8;
            float b0 = bias[col], b1 = bias[col + 1];
            float v0 = acc[i][j][0] + b0;
            float v1 = acc[i][j][1] + b1;
            float v2 = acc[i][j][2] + b0;
            float v3 = acc[i][j][3] + b1;
            if (EPI == 1) {
                const float* rp0 = res + (size_t)row * N + col;
                const float* rp1 = res + (size_t)(row + 8) * N + col;
                v0 += rp0[0]; v1 += rp0[1];
                v2 += rp1[0]; v3 += rp1[1];
            }
            if (EPI >= 2) {
                if (EPI == 2) {
                    v0 = 0.5f * v0 * (1.0f + erff(v0 * 0.70710678118654752f));
                    v1 = 0.5f * v1 * (1.0f + erff(v1 * 0.70710678118654752f));
                    v2 = 0.5f * v2 * (1.0f + erff(v2 * 0.70710678118654752f));
                    v3 = 0.5f * v3 * (1.0f + erff(v3 * 0.70710678118654752f));
                }
                __nv_bfloat16 h0 = __float2bfloat16(v0);
                __nv_bfloat16 h1 = __float2bfloat16(v1);
                __nv_bfloat16 h2 = __float2bfloat16(v2);
                __nv_bfloat16 h3 = __float2bfloat16(v3);
                *(__nv_bfloat162*)(Ch + (size_t)row * N + col) = __nv_bfloat162(h0, h1);
                *(__nv_bfloat162*)(Ch + (size_t)(row + 8) * N + col) = __nv_bfloat162(h2, h3);
                *(__nv_bfloat162*)(Cl + (size_t)row * N + col) =
                    __nv_bfloat162(__float2bfloat16(v0 - __bfloat162float(h0)),
                                   __float2bfloat16(v1 - __bfloat162float(h1)));
                *(__nv_bfloat162*)(Cl + (size_t)(row + 8) * N + col) =
                    __nv_bfloat162(__float2bfloat16(v2 - __bfloat162float(h2)),
                                   __float2bfloat16(v3 - __bfloat162float(h3)));
            } else {
                *(float2*)(Co + (size_t)row * N + col) = make_float2(v0, v1);
                *(float2*)(Co + (size_t)(row + 8) * N + col) = make_float2(v2, v3);
            }
        }
    }
}

// ---------------------------------------------------------------------------
// Weight prep: W[K,N] fp32 -> Wt hi/lo bf16 [N,K]
// ---------------------------------------------------------------------------
__global__ __launch_bounds__(256) void wtrans_kernel(
    const float* __restrict__ W, __nv_bfloat16* __restrict__ Th,
    __nv_bfloat16* __restrict__ Tl, int K, int N)
{
    __shared__ float t[32][33];
    int n0 = blockIdx.x * 32, k0 = blockIdx.y * 32;
    int tx = threadIdx.x & 31, ty = threadIdx.x >> 5;
    #pragma unroll
    for (int i = 0; i < 4; i++) {
        int kr = ty * 4 + i;
        t[kr][tx] = W[(size_t)(k0 + kr) * N + n0 + tx];
    }
    __syncthreads();
    #pragma unroll
    for (int i = 0; i < 4; i++) {
        int nr = ty * 4 + i;
        float v = t[tx][nr];
        size_t o = (size_t)(n0 + nr) * K + k0 + tx;
        __nv_bfloat16 hv = __float2bfloat16(v);
        Th[o] = hv;
        Tl[o] = __float2bfloat16(v - __bfloat162float(hv));
    }
}

// ---------------------------------------------------------------------------
// LayerNorm -> bf16 hi/lo outputs. One block per row, 256 threads, float4.
// ---------------------------------------------------------------------------
__global__ __launch_bounds__(256) void ln_kernel(
    const float* __restrict__ x, const float* __restrict__ g,
    const float* __restrict__ b, __nv_bfloat16* __restrict__ yh,
    __nv_bfloat16* __restrict__ yl)
{
    __shared__ float sh[16];
    int row = blockIdx.x;
    int t = threadIdx.x;
    const float4* xr = (const float4*)(x + (size_t)row * DIM);
    float4 v = xr[t];
    float s  = v.x + v.y + v.z + v.w;
    float s2 = v.x*v.x + v.y*v.y + v.z*v.z + v.w*v.w;
    #pragma unroll
    for (int o = 16; o > 0; o >>= 1) {
        s  += __shfl_xor_sync(0xffffffffu, s,  o);
        s2 += __shfl_xor_sync(0xffffffffu, s2, o);
    }
    if ((t & 31) == 0) { sh[t >> 5] = s; sh[8 + (t >> 5)] = s2; }
    __syncthreads();
    if (t < 32) {
        float a  = (t < 8) ? sh[t]     : 0.0f;
        float a2 = (t < 8) ? sh[8 + t] : 0.0f;
        #pragma unroll
        for (int o = 4; o > 0; o >>= 1) {
            a  += __shfl_xor_sync(0xffffffffu, a,  o);
            a2 += __shfl_xor_sync(0xffffffffu, a2, o);
        }
        if (t == 0) { sh[0] = a; sh[1] = a2; }
    }
    __syncthreads();
    float mean = sh[0] * (1.0f / DIM);
    float var  = sh[1] * (1.0f / DIM) - mean * mean;
    float rstd = rsqrtf(var + 1e-5f);
    float4 gg = ((const float4*)g)[t];
    float4 bb = ((const float4*)b)[t];
    float o0 = (v.x - mean) * rstd * gg.x + bb.x;
    float o1 = (v.y - mean) * rstd * gg.y + bb.y;
    float o2 = (v.z - mean) * rstd * gg.z + bb.z;
    float o3 = (v.w - mean) * rstd * gg.w + bb.w;
    __nv_bfloat16 h0 = __float2bfloat16(o0);
    __nv_bfloat16 h1 = __float2bfloat16(o1);
    __nv_bfloat16 h2 = __float2bfloat16(o2);
    __nv_bfloat16 h3 = __float2bfloat16(o3);
    size_t o = (size_t)row * DIM + t * 4;
    __nv_bfloat162* hp = (__nv_bfloat162*)(yh + o);
    hp[0] = __nv_bfloat162(h0, h1);
    hp[1] = __nv_bfloat162(h2, h3);
    __nv_bfloat162* lp = (__nv_bfloat162*)(yl + o);
    lp[0] = __nv_bfloat162(__float2bfloat16(o0 - __bfloat162float(h0)),
                           __float2bfloat16(o1 - __bfloat162float(h1)));
    lp[1] = __nv_bfloat162(__float2bfloat16(o2 - __bfloat162float(h2)),
                           __float2bfloat16(o3 - __bfloat162float(h3)));
}

// ---------------------------------------------------------------------------
// Flash attention on mma.sync, bf16 hi/lo in/out.
// CTA: 128 queries x one (b,h). 8 warps, 16 q-rows each. kv tiles of 64.
// qkv hi/lo layout: [B*S, 3*DIM]; q at h*64, k at DIM+h*64, v at 2*DIM+h*64.
// ---------------------------------------------------------------------------
#define AT_STRIDE 72                 // bf16 elems per smem row (144 B)
#define AT_ROWB   (AT_STRIDE * 2)    // 144
#define AT_TILE   (64 * AT_ROWB)     // 9216
#define AT_STAGE  (4 * AT_TILE)      // 36864 (Kh,Kl,Vh,Vl)
#define ATTN_SMEM (2 * AT_STAGE)     // 73728

__global__ __launch_bounds__(256) void attn_mma(
    const __nv_bfloat16* __restrict__ qkvh,
    const __nv_bfloat16* __restrict__ qkvl,
    __nv_bfloat16* __restrict__ oh, __nv_bfloat16* __restrict__ ol)
{
    extern __shared__ char sm_raw[];
    uint32_t sb = smem_u32(sm_raw);

    int tid  = threadIdx.x;
    int w    = tid >> 5;
    int lane = tid & 31;
    int qb   = (int)(gridDim.x - 1 - blockIdx.x);   // long CTAs first
    int bhid = blockIdx.y;
    int b    = bhid >> 4;
    int h    = bhid & 15;
    int q0   = qb * 128;
    const int D3 = 3 * DIM;
    size_t rowbase = (size_t)(b * SEQ) * D3 + h * 64;

    // ---- Load Q hi/lo into smem (temporarily in stage 0 area) ----
    #pragma unroll
    for (int it = 0; it < 8; it++) {
        int idx = it * 256 + tid;            // 0..2047
        int mat = idx >> 10;                 // 0: hi, 1: lo
        int rem = idx & 1023;
        int row = rem >> 3;                  // 0..127
        int c   = rem & 7;                   // 16B chunk
        const __nv_bfloat16* src =
            (mat ? qkvl : qkvh) + rowbase + (size_t)(q0 + row) * D3 + c * 8;
        *(uint4*)(sm_raw + mat * (128 * AT_ROWB) + row * AT_ROWB + c * 16) =
            *(const uint4*)src;
    }
    __syncthreads();

    // Extract Q fragments (A-frag, m16 rows x k64)
    uint32_t qfh[4][4], qfl[4][4];
    {
        int row = w * 16 + (lane & 15);
        uint32_t boff = (uint32_t)(row * AT_ROWB) + (uint32_t)((lane >> 4) * 16);
        #pragma unroll
        for (int kk = 0; kk < 4; kk++) {
            ldsm4(qfh[kk], sb + boff + kk * 32);
            ldsm4(qfl[kk], sb + 128 * AT_ROWB + boff + kk * 32);
        }
    }
    __syncthreads();

    // Per-thread softmax state (rows r and r+8 of the warp's 16)
    float m2[2] = { -1e30f, -1e30f };
    float l2[2] = { 0.0f, 0.0f };
    float oacc[8][4];
    #pragma unroll
    for (int j = 0; j < 8; j++)
        #pragma unroll
        for (int q = 0; q < 4; q++) oacc[j][q] = 0.0f;

    const __nv_bfloat16* kv_srcs[4] = {
        qkvh + rowbase + DIM,       qkvl + rowbase + DIM,
        qkvh + rowbase + 2 * DIM,   qkvl + rowbase + 2 * DIM };

    auto load_kv = [&](int kt, int s) {
        #pragma unroll
        for (int it = 0; it < 8; it++) {
            int idx = it * 256 + tid;        // 0..2047
            int mat = idx >> 9;              // 0..3 (Kh,Kl,Vh,Vl)
            int rem = idx & 511;
            int row = rem >> 3;              // 0..63
            int c   = rem & 7;
            const __nv_bfloat16* src =
                kv_srcs[mat] + (size_t)(kt * 64 + row) * D3 + c * 8;
            cp16(sb + s * AT_STAGE + mat * AT_TILE + row * AT_ROWB + c * 16, src);
        }
        CP_COMMIT();
    };

    int ktmax = 2 * qb + 1;
    load_kv(0, 0);

    int qrow0 = q0 + w * 16 + (lane >> 2);

    for (int kt = 0; kt <= ktmax; kt++) {
        int s = kt & 1;
        if (kt < ktmax) { load_kv(kt + 1, s ^ 1); CP_WAIT1(); }
        else            { CP_WAIT0(); }
        __syncthreads();

        bool active = (kt * 64 <= q0 + w * 16 + 15);
        if (active) {
            uint32_t kb_h = sb + s * AT_STAGE;
            uint32_t kb_l = kb_h + AT_TILE;
            uint32_t vb_h = kb_h + 2 * AT_TILE;
            uint32_t vb_l = kb_h + 3 * AT_TILE;

            // ---- S = Q K^T (hi/lo 3-pass) ----
            float sacc[8][4];
            #pragma unroll
            for (int j = 0; j < 8; j++)
                #pragma unroll
                for (int q = 0; q < 4; q++) sacc[j][q] = 0.0f;

            int bm   = lane >> 3;
            int bkh  = bm & 1;
            int bjj  = bm >> 1;
            int brow = (lane & 7) + bjj * 8;
            #pragma unroll
            for (int jp = 0; jp < 4; jp++) {
                #pragma unroll
                for (int kk = 0; kk < 4; kk++) {
                    uint32_t off = (uint32_t)((jp * 16 + brow) * AT_ROWB)
                                 + (uint32_t)((bkh * 8 + kk * 16) * 2);
                    uint32_t khr[4], klr[4];
                    ldsm4(khr, kb_h + off);
                    ldsm4(klr, kb_l + off);
                    mma16816(sacc[2 * jp],     qfh[kk], khr[0], khr[1]);
                    mma16816(sacc[2 * jp + 1], qfh[kk], khr[2], khr[3]);
                    mma16816(sacc[2 * jp],     qfl[kk], khr[0], khr[1]);
                    mma16816(sacc[2 * jp + 1], qfl[kk], khr[2], khr[3]);
                    mma16816(sacc[2 * jp],     qfh[kk], klr[0], klr[1]);
                    mma16816(sacc[2 * jp + 1], qfh[kk], klr[2], klr[3]);
                }
            }

            // ---- scale + causal mask + online softmax ----
            bool needmask = (kt * 64 + 63 > q0 + w * 16);
            #pragma unroll
            for (int hh = 0; hh < 2; hh++) {
                int qrow = qrow0 + hh * 8;
                #pragma unroll
                for (int j = 0; j < 8; j++) {
                    #pragma unroll
                    for (int c = 0; c < 2; c++) {
                        float v = sacc[j][2 * hh + c] * 0.125f;
                        if (needmask) {
                            int kv = kt * 64 + j * 8 + (lane & 3) * 2 + c;
                            if (kv > qrow) v = -1e30f;
                        }
                        sacc[j][2 * hh + c] = v;
                    }
                }
                float mx = -1e30f;
                #pragma unroll
                for (int j = 0; j < 8; j++)
                    mx = fmaxf(mx, fmaxf(sacc[j][2 * hh], sacc[j][2 * hh + 1]));
                mx = fmaxf(mx, __shfl_xor_sync(0xffffffffu, mx, 1));
                mx = fmaxf(mx, __shfl_xor_sync(0xffffffffu, mx, 2));
                float mn = fmaxf(m2[hh], mx);
                float sum = 0.0f;
                #pragma unroll
                for (int j = 0; j < 8; j++) {
                    float p0 = __expf(sacc[j][2 * hh]     - mn);
                    float p1 = __expf(sacc[j][2 * hh + 1] - mn);
                    sacc[j][2 * hh]     = p0;
                    sacc[j][2 * hh + 1] = p1;
                    sum += p0 + p1;
                }
                sum += __shfl_xor_sync(0xffffffffu, sum, 1);
                sum += __shfl_xor_sync(0xffffffffu, sum, 2);
                float alpha = __expf(m2[hh] - mn);
                m2[hh] = mn;
                l2[hh] = l2[hh] * alpha + sum;
                #pragma unroll
                for (int j = 0; j < 8; j++) {
                    oacc[j][2 * hh]     *= alpha;
                    oacc[j][2 * hh + 1] *= alpha;
                }
            }

            // ---- pack P to bf16 hi/lo A-fragments ----
            uint32_t pah[4][4], pal[4][4];
            #pragma unroll
            for (int kk = 0; kk < 4; kk++) {
                #pragma unroll
                for (int t = 0; t < 4; t++) {
                    int j  = 2 * kk + (t >> 1);
                    int ci = (t & 1) * 2;
                    float v0 = sacc[j][ci], v1 = sacc[j][ci + 1];
                    __nv_bfloat16 h0 = __float2bfloat16(v0);
                    __nv_bfloat16 h1 = __float2bfloat16(v1);
                    pah[kk][t] = pk2(h0, h1);
                    pal[kk][t] = pk2(__float2bfloat16(v0 - __bfloat162float(h0)),
                                     __float2bfloat16(v1 - __bfloat162float(h1)));
                }
            }

            // ---- O += P V (hi/lo 3-pass), V via trans ldmatrix ----
            int r   = lane & 7;
            int mm  = lane >> 3;
            #pragma unroll
            for (int jp = 0; jp < 4; jp++) {
                #pragma unroll
                for (int kk = 0; kk < 4; kk++) {
                    uint32_t off = (uint32_t)((kk * 16 + r + (mm & 1) * 8) * AT_ROWB)
                                 + (uint32_t)((jp * 16 + (mm >> 1) * 8) * 2);
                    uint32_t vhr[4], vlr[4];
                    ldsm4t(vhr, vb_h + off);
                    ldsm4t(vlr, vb_l + off);
                    mma16816(oacc[2 * jp],     pah[kk], vhr[0], vhr[1]);
                    mma16816(oacc[2 * jp + 1], pah[kk], vhr[2], vhr[3]);
                    mma16816(oacc[2 * jp],     pal[kk], vhr[0], vhr[1]);
                    mma16816(oacc[2 * jp + 1], pal[kk], vhr[2], vhr[3]);
                    mma16816(oacc[2 * jp],     pah[kk], vlr[0], vlr[1]);
                    mma16816(oacc[2 * jp + 1], pah[kk], vlr[2], vlr[3]);
                }
            }
        }
        __syncthreads();
    }

    // ---- normalize + write hi/lo output ----
    float inv0 = 1.0f / l2[0];
    float inv1 = 1.0f / l2[1];
    size_t obase = (size_t)(b * SEQ) * DIM + h * 64;
    int row1 = q0 + w * 16 + (lane >> 2);
    int colb = (lane & 3) * 2;
    #pragma unroll
    for (int j = 0; j < 8; j++) {
        int col = j * 8 + colb;
        float v0 = oacc[j][0] * inv0;
        float v1 = oacc[j][1] * inv0;
        float v2 = oacc[j][2] * inv1;
        float v3 = oacc[j][3] * inv1;
        __nv_bfloat16 h0 = __float2bfloat16(v0);
        __nv_bfloat16 h1 = __float2bfloat16(v1);
        __nv_bfloat16 h2 = __float2bfloat16(v2);
        __nv_bfloat16 h3 = __float2bfloat16(v3);
        *(__nv_bfloat162*)(oh + obase + (size_t)row1 * DIM + col) = __nv_bfloat162(h0, h1);
        *(__nv_bfloat162*)(oh + obase + (size_t)(row1 + 8) * DIM + col) = __nv_bfloat162(h2, h3);
        *(__nv_bfloat162*)(ol + obase + (size_t)row1 * DIM + col) =
            __nv_bfloat162(__float2bfloat16(v0 - __bfloat162float(h0)),
                           __float2bfloat16(v1 - __bfloat162float(h1)));
        *(__nv_bfloat162*)(ol + obase + (size_t)(row1 + 8) * DIM + col) =
            __nv_bfloat162(__float2bfloat16(v2 - __bfloat162float(h2)),
                           __float2bfloat16(v3 - __bfloat162float(h3)));
    }
}

// ---------------------------------------------------------------------------
// Launch
// ---------------------------------------------------------------------------
extern "C" void kernel_launch(void* const* d_in, const int* in_sizes, int n_in,
                              void* d_out, int out_size)
{
    const float* x      = (const float*)d_in[0];
    const float* W_qkv  = (const float*)d_in[1];
    const float* b_qkv  = (const float*)d_in[2];
    const float* W_o    = (const float*)d_in[3];
    const float* b_o    = (const float*)d_in[4];
    const float* W_fc   = (const float*)d_in[5];
    const float* b_fc   = (const float*)d_in[6];
    const float* W_pr   = (const float*)d_in[7];
    const float* b_pr   = (const float*)d_in[8];
    const float* g1     = (const float*)d_in[9];
    const float* beta1  = (const float*)d_in[10];
    const float* g2     = (const float*)d_in[11];
    const float* beta2  = (const float*)d_in[12];
    float* out = (float*)d_out;

    __nv_bfloat16 *pWqh, *pWql, *pWoh, *pWol, *pWfh, *pWfl, *pWph, *pWpl;
    __nv_bfloat16 *phh, *phl, *pqh, *pql, *path, *patl, *ph2h, *ph2l, *pfch, *pfcl;
    float *px1;
    cudaGetSymbolAddress((void**)&pWqh, g_Wqkv_h);
    cudaGetSymbolAddress((void**)&pWql, g_Wqkv_l);
    cudaGetSymbolAddress((void**)&pWoh, g_Wo_h);
    cudaGetSymbolAddress((void**)&pWol, g_Wo_l);
    cudaGetSymbolAddress((void**)&pWfh, g_Wfc_h);
    cudaGetSymbolAddress((void**)&pWfl, g_Wfc_l);
    cudaGetSymbolAddress((void**)&pWph, g_Wpr_h);
    cudaGetSymbolAddress((void**)&pWpl, g_Wpr_l);
    cudaGetSymbolAddress((void**)&phh,  g_h_h);
    cudaGetSymbolAddress((void**)&phl,  g_h_l);
    cudaGetSymbolAddress((void**)&pqh,  g_qkv_h);
    cudaGetSymbolAddress((void**)&pql,  g_qkv_l);
    cudaGetSymbolAddress((void**)&path, g_att_h);
    cudaGetSymbolAddress((void**)&patl, g_att_l);
    cudaGetSymbolAddress((void**)&px1,  g_x1);
    cudaGetSymbolAddress((void**)&ph2h, g_h2_h);
    cudaGetSymbolAddress((void**)&ph2l, g_h2_l);
    cudaGetSymbolAddress((void**)&pfch, g_fc_h);
    cudaGetSymbolAddress((void**)&pfcl, g_fc_l);

    cudaFuncSetAttribute(attn_mma,
                         cudaFuncAttributeMaxDynamicSharedMemorySize, ATTN_SMEM);
    cudaFuncSetAttribute(gemm_mma<0>,
                         cudaFuncAttributeMaxDynamicSharedMemorySize, GEMM_SMEM);
    cudaFuncSetAttribute(gemm_mma<1>,
                         cudaFuncAttributeMaxDynamicSharedMemorySize, GEMM_SMEM);
    cudaFuncSetAttribute(gemm_mma<2>,
                         cudaFuncAttributeMaxDynamicSharedMemorySize, GEMM_SMEM);
    cudaFuncSetAttribute(gemm_mma<3>,
                         cudaFuncAttributeMaxDynamicSharedMemorySize, GEMM_SMEM);

    // Weight prep (transpose + hi/lo split)
    wtrans_kernel<<<dim3(3072 / 32, 1024 / 32), 256>>>(W_qkv, pWqh, pWql, 1024, 3072);
    wtrans_kernel<<<dim3(1024 / 32, 1024 / 32), 256>>>(W_o,   pWoh, pWol, 1024, 1024);
    wtrans_kernel<<<dim3(4096 / 32, 1024 / 32), 256>>>(W_fc,  pWfh, pWfl, 1024, 4096);
    wtrans_kernel<<<dim3(1024 / 32, 4096 / 32), 256>>>(W_pr,  pWph, pWpl, 4096, 1024);

    // 1. LN1 -> h (hi/lo)
    ln_kernel<<<MROWS, 256>>>(x, g1, beta1, phh, phl);
    // 2. QKV projection -> bf16 hi/lo
    gemm_mma<3><<<dim3(3072 / 128, MROWS / 128), 256, GEMM_SMEM>>>(
        phh, phl, pWqh, pWql, b_qkv, nullptr, nullptr, pqh, pql,
        MROWS, 3 * DIM, DIM);
    // 3. Attention (tensor-core flash) -> att hi/lo
    attn_mma<<<dim3(SEQ / 128, BATCH * NHEAD), 256, ATTN_SMEM>>>(
        pqh, pql, path, patl);
    // 4. Output projection + residual -> x1
    gemm_mma<1><<<dim3(DIM / 128, MROWS / 128), 256, GEMM_SMEM>>>(
        path, patl, pWoh, pWol, b_o, x, px1, nullptr, nullptr,
        MROWS, DIM, DIM);
    // 5. LN2 -> h2 (hi/lo)
    ln_kernel<<<MROWS, 256>>>(px1, g2, beta2, ph2h, ph2l);
    // 6. FC + GELU -> fc (hi/lo)
    gemm_mma<2><<<dim3(4 * DIM / 128, MROWS / 128), 256, GEMM_SMEM>>>(
        ph2h, ph2l, pWfh, pWfl, b_fc, nullptr, nullptr, pfch, pfcl,
        MROWS, 4 * DIM, DIM);
    // 7. Projection + residual -> out
    gemm_mma<1><<<dim3(DIM / 128, MROWS / 128), 256, GEMM_SMEM>>>(
        pfch, pfcl, pWph, pWpl, b_pr, px1, out, nullptr, nullptr,
        MROWS, DIM, 4 * DIM);
}

// round 5
// speedup vs baseline: 2.4467x; 1.0648x over previous
#include <cuda_runtime.h>
#include <cuda_bf16.h>
#include <math.h>
#include <stdint.h>
#include <string.h>

// Problem constants
#define BATCH 2
#define SEQ   2048
#define DIM   1024
#define NHEAD 16
#define HDIM  64
#define MROWS (BATCH * SEQ)   // 4096

// ---------------------------------------------------------------------------
// Scratch (no allocations allowed -> __device__ globals)
// ---------------------------------------------------------------------------
__device__ __nv_bfloat16 g_Wqkv_h[3072 * 1024];
__device__ __nv_bfloat16 g_Wqkv_l[3072 * 1024];
__device__ __nv_bfloat16 g_Wo_h  [1024 * 1024];
__device__ __nv_bfloat16 g_Wo_l  [1024 * 1024];
__device__ __nv_bfloat16 g_Wfc_h [4096 * 1024];
__device__ __nv_bfloat16 g_Wfc_l [4096 * 1024];
__device__ __nv_bfloat16 g_Wpr_h [1024 * 4096];
__device__ __nv_bfloat16 g_Wpr_l [1024 * 4096];

__device__ __nv_bfloat16 g_h_h [MROWS * DIM];
__device__ __nv_bfloat16 g_h_l [MROWS * DIM];
__device__ __nv_bfloat16 g_qkv_h[MROWS * 3 * DIM];
__device__ __nv_bfloat16 g_qkv_l[MROWS * 3 * DIM];
__device__ __nv_bfloat16 g_att_h[MROWS * DIM];
__device__ __nv_bfloat16 g_att_l[MROWS * DIM];
__device__ float         g_x1  [MROWS * DIM];
__device__ __nv_bfloat16 g_h2_h[MROWS * DIM];
__device__ __nv_bfloat16 g_h2_l[MROWS * DIM];
__device__ __nv_bfloat16 g_fc_h[MROWS * 4 * DIM];
__device__ __nv_bfloat16 g_fc_l[MROWS * 4 * DIM];

// ---------------------------------------------------------------------------
// PTX helpers (family-common only: cp.async, ldmatrix, mma.sync)
// ---------------------------------------------------------------------------
__device__ __forceinline__ uint32_t smem_u32(const void* p) {
    uint32_t a;
    asm("{ .reg .u64 t; cvta.to.shared.u64 t, %1; cvt.u32.u64 %0, t; }"
        : "=r"(a) : "l"(p));
    return a;
}

__device__ __forceinline__ void cp16(uint32_t dst, const void* src) {
    asm volatile("cp.async.cg.shared.global [%0], [%1], 16;"
                 :: "r"(dst), "l"(src));
}
#define CP_COMMIT() asm volatile("cp.async.commit_group;" ::: "memory")
#define CP_WAIT2()  asm volatile("cp.async.wait_group 2;" ::: "memory")
#define CP_WAIT1()  asm volatile("cp.async.wait_group 1;" ::: "memory")
#define CP_WAIT0()  asm volatile("cp.async.wait_group 0;" ::: "memory")

__device__ __forceinline__ void ldsm4(uint32_t* r, uint32_t a) {
    asm volatile("ldmatrix.sync.aligned.m8n8.x4.shared.b16 {%0,%1,%2,%3}, [%4];"
                 : "=r"(r[0]), "=r"(r[1]), "=r"(r[2]), "=r"(r[3]) : "r"(a));
}
__device__ __forceinline__ void ldsm4t(uint32_t* r, uint32_t a) {
    asm volatile("ldmatrix.sync.aligned.m8n8.x4.trans.shared.b16 {%0,%1,%2,%3}, [%4];"
                 : "=r"(r[0]), "=r"(r[1]), "=r"(r[2]), "=r"(r[3]) : "r"(a));
}

__device__ __forceinline__ void mma16816(float* d, const uint32_t* a,
                                         uint32_t b0, uint32_t b1) {
    asm volatile(
        "mma.sync.aligned.m16n8k16.row.col.f32.bf16.bf16.f32 "
        "{%0,%1,%2,%3}, {%4,%5,%6,%7}, {%8,%9}, {%0,%1,%2,%3};"
        : "+f"(d[0]), "+f"(d[1]), "+f"(d[2]), "+f"(d[3])
        : "r"(a[0]), "r"(a[1]), "r"(a[2]), "r"(a[3]), "r"(b0), "r"(b1));
}

__device__ __forceinline__ uint32_t pk2(__nv_bfloat16 a, __nv_bfloat16 b) {
    __nv_bfloat162 t(a, b);
    uint32_t r;
    memcpy(&r, &t, 4);
    return r;
}

// ---------------------------------------------------------------------------
// bf16 mma.sync GEMM with hi/lo 3-term compensation.
// C[M,N] = epi(sum_k A[m,k]*Bt[n,k]), A hi/lo [M,K] K-major, Bt hi/lo [N,K].
// Block tile 128x256x32, 8 warps (2x4), warp tile 64x64. 3-stage cp.async.
// EPI: 0 = +bias -> fp32; 1 = +bias+res -> fp32; 2 = gelu(+bias) -> bf16 hi/lo
//      3 = +bias -> bf16 hi/lo
// ---------------------------------------------------------------------------
#define TS 40                        // smem row stride in bf16 elems (80 bytes)
#define TILE_A (128 * TS * 2)        // 10240 bytes (128-row tile)
#define TILE_BB (256 * TS * 2)       // 20480 bytes (256-row tile)
#define STAGE_B (2 * TILE_A + 2 * TILE_BB)   // 61440
#define GEMM_SMEM (3 * STAGE_B)      // 184320

template <int EPI>
__global__ __launch_bounds__(256, 1) void gemm_mma(
    const __nv_bfloat16* __restrict__ Ah, const __nv_bfloat16* __restrict__ Al,
    const __nv_bfloat16* __restrict__ Bh, const __nv_bfloat16* __restrict__ Bl,
    const float* __restrict__ bias, const float* __restrict__ res,
    float* __restrict__ Co, __nv_bfloat16* __restrict__ Ch,
    __nv_bfloat16* __restrict__ Cl, int M, int N, int K)
{
    extern __shared__ char sm_raw[];
    uint32_t sb = smem_u32(sm_raw);

    int tid  = threadIdx.x;
    int w    = tid >> 5;
    int lane = tid & 31;
    int wm   = w >> 2;               // 0..1  (64-row group)
    int wn   = w & 3;                // 0..3  (64-col group)
    int n0   = blockIdx.x * 256;
    int m0   = blockIdx.y * 128;

    const __nv_bfloat16* srcA[2] = { Ah + (size_t)m0 * K, Al + (size_t)m0 * K };
    const __nv_bfloat16* srcB[2] = { Bh + (size_t)n0 * K, Bl + (size_t)n0 * K };

    float acc[4][8][4];
    #pragma unroll
    for (int i = 0; i < 4; i++)
        #pragma unroll
        for (int j = 0; j < 8; j++)
            #pragma unroll
            for (int q = 0; q < 4; q++) acc[i][j][q] = 0.0f;

    int nch = K >> 5;                // K/32

    // stage loader: A 2x128 rows + B 2x256 rows, 4 chunks(16B) each = 3072 cp
    auto load_stage = [&](int c, int s) {
        int k0 = c << 5;
        uint32_t stg = sb + s * STAGE_B;
        #pragma unroll
        for (int it = 0; it < 12; it++) {
            int idx = it * 256 + tid;          // 0..3071
            const __nv_bfloat16* src;
            uint32_t dst;
            if (idx < 1024) {                  // A tiles: 2 x 128 rows x 4 chunks
                int mat   = idx >> 9;          // 0..1
                int row   = (idx >> 2) & 127;
                int chunk = idx & 3;
                src = srcA[mat] + (size_t)row * K + k0 + chunk * 8;
                dst = stg + mat * TILE_A + (uint32_t)(row * TS + chunk * 8) * 2;
            } else {                           // B tiles: 2 x 256 rows x 4 chunks
                int idx2  = idx - 1024;
                int mat   = idx2 >> 10;        // 0..1
                int row   = (idx2 >> 2) & 255;
                int chunk = idx2 & 3;
                src = srcB[mat] + (size_t)row * K + k0 + chunk * 8;
                dst = stg + 2 * TILE_A + mat * TILE_BB
                    + (uint32_t)(row * TS + chunk * 8) * 2;
            }
            cp16(dst, src);
        }
        CP_COMMIT();
    };

    load_stage(0, 0);
    if (nch > 1) load_stage(1, 1);
    if (nch > 2) load_stage(2, 2);

    int arow = wm * 64 + (lane & 15);
    uint32_t a_off = (uint32_t)(arow * TS + (lane >> 4) * 8) * 2;
    int bmat = lane >> 3;                 // 0..3
    int b_h  = bmat & 1;                  // k half
    int b_j  = bmat >> 1;                 // n8 tile within 16-col group
    uint32_t b_off = (uint32_t)((wn * 64 + b_j * 8 + (lane & 7)) * TS + b_h * 8) * 2;

    for (int c = 0; c < nch; c++) {
        int s = c % 3;
        int rem = nch - 1 - c;
        if (rem >= 2) { CP_WAIT2(); }
        else if (rem == 1) { CP_WAIT1(); }
        else { CP_WAIT0(); }
        __syncthreads();

        uint32_t stg = sb + s * STAGE_B;
        uint32_t pAh = stg;
        uint32_t pAl = stg + TILE_A;
        uint32_t pBh = stg + 2 * TILE_A;
        uint32_t pBl = stg + 2 * TILE_A + TILE_BB;

        #pragma unroll
        for (int kk = 0; kk < 32; kk += 16) {
            uint32_t kb = (uint32_t)kk * 2;
            uint32_t ah[4][4], al[4][4];
            #pragma unroll
            for (int i = 0; i < 4; i++) {
                ldsm4(ah[i], pAh + a_off + kb + (uint32_t)i * 16 * TS * 2);
                ldsm4(al[i], pAl + a_off + kb + (uint32_t)i * 16 * TS * 2);
            }
            #pragma unroll
            for (int g = 0; g < 4; g++) {          // 16-col groups
                uint32_t boff = b_off + (uint32_t)g * 16 * TS * 2 + kb;
                uint32_t bh[4], bl[4];
                ldsm4(bh, pBh + boff);
                ldsm4(bl, pBl + boff);
                int j0 = 2 * g, j1 = 2 * g + 1;
                #pragma unroll
                for (int i = 0; i < 4; i++) {
                    mma16816(acc[i][j0], ah[i], bh[0], bh[1]);
                    mma16816(acc[i][j1], ah[i], bh[2], bh[3]);
                    mma16816(acc[i][j0], ah[i], bl[0], bl[1]);
                    mma16816(acc[i][j1], ah[i], bl[2], bl[3]);
                    mma16816(acc[i][j0], al[i], bh[0], bh[1]);
                    mma16816(acc[i][j1], al[i], bh[2], bh[3]);
                }
            }
        }
        __syncthreads();
        if (c + 3 < nch) load_stage(c + 3, s);
    }

    // Epilogue
    int r0 = m0 + wm * 64 + (lane >> 2);
    int c0 = n0 + wn * 64 + (lane & 3) * 2;
    #pragma unroll
    for (int i = 0; i < 4; i++) {
        int row = r0 + i * 16;
        #pragma unroll
        for (int j = 0; j < 8; j++) {
            int col = c0 + j * 8;
            float b0 = bias[col], b1 = bias[col + 1];
            float v0 = acc[i][j][0] + b0;
            float v1 = acc[i][j][1] + b1;
            float v2 = acc[i][j][2] + b0;
            float v3 = acc[i][j][3] + b1;
            if (EPI == 1) {
                const float* rp0 = res + (size_t)row * N + col;
                const float* rp1 = res + (size_t)(row + 8) * N + col;
                v0 += rp0[0]; v1 += rp0[1];
                v2 += rp1[0]; v3 += rp1[1];
            }
            if (EPI >= 2) {
                if (EPI == 2) {
                    v0 = 0.5f * v0 * (1.0f + erff(v0 * 0.70710678118654752f));
                    v1 = 0.5f * v1 * (1.0f + erff(v1 * 0.70710678118654752f));
                    v2 = 0.5f * v2 * (1.0f + erff(v2 * 0.70710678118654752f));
                    v3 = 0.5f * v3 * (1.0f + erff(v3 * 0.70710678118654752f));
                }
                __nv_bfloat16 h0 = __float2bfloat16(v0);
                __nv_bfloat16 h1 = __float2bfloat16(v1);
                __nv_bfloat16 h2 = __float2bfloat16(v2);
                __nv_bfloat16 h3 = __float2bfloat16(v3);
                *(__nv_bfloat162*)(Ch + (size_t)row * N + col) = __nv_bfloat162(h0, h1);
                *(__nv_bfloat162*)(Ch + (size_t)(row + 8) * N + col) = __nv_bfloat162(h2, h3);
                *(__nv_bfloat162*)(Cl + (size_t)row * N + col) =
                    __nv_bfloat162(__float2bfloat16(v0 - __bfloat162float(h0)),
                                   __float2bfloat16(v1 - __bfloat162float(h1)));
                *(__nv_bfloat162*)(Cl + (size_t)(row + 8) * N + col) =
                    __nv_bfloat162(__float2bfloat16(v2 - __bfloat162float(h2)),
                                   __float2bfloat16(v3 - __bfloat162float(h3)));
            } else {
                *(float2*)(Co + (size_t)row * N + col) = make_float2(v0, v1);
                *(float2*)(Co + (size_t)(row + 8) * N + col) = make_float2(v2, v3);
            }
        }
    }
}

// ---------------------------------------------------------------------------
// Weight prep: W[K,N] fp32 -> Wt hi/lo bf16 [N,K]
// ---------------------------------------------------------------------------
__global__ __launch_bounds__(256) void wtrans_kernel(
    const float* __restrict__ W, __nv_bfloat16* __restrict__ Th,
    __nv_bfloat16* __restrict__ Tl, int K, int N)
{
    __shared__ float t[32][33];
    int n0 = blockIdx.x * 32, k0 = blockIdx.y * 32;
    int tx = threadIdx.x & 31, ty = threadIdx.x >> 5;
    #pragma unroll
    for (int i = 0; i < 4; i++) {
        int kr = ty * 4 + i;
        t[kr][tx] = W[(size_t)(k0 + kr) * N + n0 + tx];
    }
    __syncthreads();
    #pragma unroll
    for (int i = 0; i < 4; i++) {
        int nr = ty * 4 + i;
        float v = t[tx][nr];
        size_t o = (size_t)(n0 + nr) * K + k0 + tx;
        __nv_bfloat16 hv = __float2bfloat16(v);
        Th[o] = hv;
        Tl[o] = __float2bfloat16(v - __bfloat162float(hv));
    }
}

// ---------------------------------------------------------------------------
// LayerNorm -> bf16 hi/lo outputs. One block per row, 256 threads, float4.
// ---------------------------------------------------------------------------
__global__ __launch_bounds__(256) void ln_kernel(
    const float* __restrict__ x, const float* __restrict__ g,
    const float* __restrict__ b, __nv_bfloat16* __restrict__ yh,
    __nv_bfloat16* __restrict__ yl)
{
    __shared__ float sh[16];
    int row = blockIdx.x;
    int t = threadIdx.x;
    const float4* xr = (const float4*)(x + (size_t)row * DIM);
    float4 v = xr[t];
    float s  = v.x + v.y + v.z + v.w;
    float s2 = v.x*v.x + v.y*v.y + v.z*v.z + v.w*v.w;
    #pragma unroll
    for (int o = 16; o > 0; o >>= 1) {
        s  += __shfl_xor_sync(0xffffffffu, s,  o);
        s2 += __shfl_xor_sync(0xffffffffu, s2, o);
    }
    if ((t & 31) == 0) { sh[t >> 5] = s; sh[8 + (t >> 5)] = s2; }
    __syncthreads();
    if (t < 32) {
        float a  = (t < 8) ? sh[t]     : 0.0f;
        float a2 = (t < 8) ? sh[8 + t] : 0.0f;
        #pragma unroll
        for (int o = 4; o > 0; o >>= 1) {
            a  += __shfl_xor_sync(0xffffffffu, a,  o);
            a2 += __shfl_xor_sync(0xffffffffu, a2, o);
        }
        if (t == 0) { sh[0] = a; sh[1] = a2; }
    }
    __syncthreads();
    float mean = sh[0] * (1.0f / DIM);
    float var  = sh[1] * (1.0f / DIM) - mean * mean;
    float rstd = rsqrtf(var + 1e-5f);
    float4 gg = ((const float4*)g)[t];
    float4 bb = ((const float4*)b)[t];
    float o0 = (v.x - mean) * rstd * gg.x + bb.x;
    float o1 = (v.y - mean) * rstd * gg.y + bb.y;
    float o2 = (v.z - mean) * rstd * gg.z + bb.z;
    float o3 = (v.w - mean) * rstd * gg.w + bb.w;
    __nv_bfloat16 h0 = __float2bfloat16(o0);
    __nv_bfloat16 h1 = __float2bfloat16(o1);
    __nv_bfloat16 h2 = __float2bfloat16(o2);
    __nv_bfloat16 h3 = __float2bfloat16(o3);
    size_t o = (size_t)row * DIM + t * 4;
    __nv_bfloat162* hp = (__nv_bfloat162*)(yh + o);
    hp[0] = __nv_bfloat162(h0, h1);
    hp[1] = __nv_bfloat162(h2, h3);
    __nv_bfloat162* lp = (__nv_bfloat162*)(yl + o);
    lp[0] = __nv_bfloat162(__float2bfloat16(o0 - __bfloat162float(h0)),
                           __float2bfloat16(o1 - __bfloat162float(h1)));
    lp[1] = __nv_bfloat162(__float2bfloat16(o2 - __bfloat162float(h2)),
                           __float2bfloat16(o3 - __bfloat162float(h3)));
}

// ---------------------------------------------------------------------------
// Flash attention on mma.sync, bf16 hi/lo in/out.
// CTA: 128 queries x one (b,h). 8 warps, 16 q-rows each. kv tiles of 64.
// ---------------------------------------------------------------------------
#define AT_STRIDE 72                 // bf16 elems per smem row (144 B)
#define AT_ROWB   (AT_STRIDE * 2)    // 144
#define AT_TILE   (64 * AT_ROWB)     // 9216
#define AT_STAGE  (4 * AT_TILE)      // 36864 (Kh,Kl,Vh,Vl)
#define ATTN_SMEM (2 * AT_STAGE)     // 73728

__global__ __launch_bounds__(256) void attn_mma(
    const __nv_bfloat16* __restrict__ qkvh,
    const __nv_bfloat16* __restrict__ qkvl,
    __nv_bfloat16* __restrict__ oh, __nv_bfloat16* __restrict__ ol)
{
    extern __shared__ char sm_raw[];
    uint32_t sb = smem_u32(sm_raw);

    int tid  = threadIdx.x;
    int w    = tid >> 5;
    int lane = tid & 31;
    int qb   = (int)(gridDim.x - 1 - blockIdx.x);   // long CTAs first
    int bhid = blockIdx.y;
    int b    = bhid >> 4;
    int h    = bhid & 15;
    int q0   = qb * 128;
    const int D3 = 3 * DIM;
    size_t rowbase = (size_t)(b * SEQ) * D3 + h * 64;

    // ---- Load Q hi/lo into smem (temporarily in stage 0 area) ----
    #pragma unroll
    for (int it = 0; it < 8; it++) {
        int idx = it * 256 + tid;
        int mat = idx >> 10;
        int rem = idx & 1023;
        int row = rem >> 3;
        int c   = rem & 7;
        const __nv_bfloat16* src =
            (mat ? qkvl : qkvh) + rowbase + (size_t)(q0 + row) * D3 + c * 8;
        *(uint4*)(sm_raw + mat * (128 * AT_ROWB) + row * AT_ROWB + c * 16) =
            *(const uint4*)src;
    }
    __syncthreads();

    uint32_t qfh[4][4], qfl[4][4];
    {
        int row = w * 16 + (lane & 15);
        uint32_t boff = (uint32_t)(row * AT_ROWB) + (uint32_t)((lane >> 4) * 16);
        #pragma unroll
        for (int kk = 0; kk < 4; kk++) {
            ldsm4(qfh[kk], sb + boff + kk * 32);
            ldsm4(qfl[kk], sb + 128 * AT_ROWB + boff + kk * 32);
        }
    }
    __syncthreads();

    float m2[2] = { -1e30f, -1e30f };
    float l2[2] = { 0.0f, 0.0f };
    float oacc[8][4];
    #pragma unroll
    for (int j = 0; j < 8; j++)
        #pragma unroll
        for (int q = 0; q < 4; q++) oacc[j][q] = 0.0f;

    const __nv_bfloat16* kv_srcs[4] = {
        qkvh + rowbase + DIM,       qkvl + rowbase + DIM,
        qkvh + rowbase + 2 * DIM,   qkvl + rowbase + 2 * DIM };

    auto load_kv = [&](int kt, int s) {
        #pragma unroll
        for (int it = 0; it < 8; it++) {
            int idx = it * 256 + tid;
            int mat = idx >> 9;
            int rem = idx & 511;
            int row = rem >> 3;
            int c   = rem & 7;
            const __nv_bfloat16* src =
                kv_srcs[mat] + (size_t)(kt * 64 + row) * D3 + c * 8;
            cp16(sb + s * AT_STAGE + mat * AT_TILE + row * AT_ROWB + c * 16, src);
        }
        CP_COMMIT();
    };

    int ktmax = 2 * qb + 1;
    load_kv(0, 0);

    int qrow0 = q0 + w * 16 + (lane >> 2);

    for (int kt = 0; kt <= ktmax; kt++) {
        int s = kt & 1;
        if (kt < ktmax) { load_kv(kt + 1, s ^ 1); CP_WAIT1(); }
        else            { CP_WAIT0(); }
        __syncthreads();

        bool active = (kt * 64 <= q0 + w * 16 + 15);
        if (active) {
            uint32_t kb_h = sb + s * AT_STAGE;
            uint32_t kb_l = kb_h + AT_TILE;
            uint32_t vb_h = kb_h + 2 * AT_TILE;
            uint32_t vb_l = kb_h + 3 * AT_TILE;

            float sacc[8][4];
            #pragma unroll
            for (int j = 0; j < 8; j++)
                #pragma unroll
                for (int q = 0; q < 4; q++) sacc[j][q] = 0.0f;

            int bm   = lane >> 3;
            int bkh  = bm & 1;
            int bjj  = bm >> 1;
            int brow = (lane & 7) + bjj * 8;
            #pragma unroll
            for (int jp = 0; jp < 4; jp++) {
                #pragma unroll
                for (int kk = 0; kk < 4; kk++) {
                    uint32_t off = (uint32_t)((jp * 16 + brow) * AT_ROWB)
                                 + (uint32_t)((bkh * 8 + kk * 16) * 2);
                    uint32_t khr[4], klr[4];
                    ldsm4(khr, kb_h + off);
                    ldsm4(klr, kb_l + off);
                    mma16816(sacc[2 * jp],     qfh[kk], khr[0], khr[1]);
                    mma16816(sacc[2 * jp + 1], qfh[kk], khr[2], khr[3]);
                    mma16816(sacc[2 * jp],     qfl[kk], khr[0], khr[1]);
                    mma16816(sacc[2 * jp + 1], qfl[kk], khr[2], khr[3]);
                    mma16816(sacc[2 * jp],     qfh[kk], klr[0], klr[1]);
                    mma16816(sacc[2 * jp + 1], qfh[kk], klr[2], klr[3]);
                }
            }

            bool needmask = (kt * 64 + 63 > q0 + w * 16);
            #pragma unroll
            for (int hh = 0; hh < 2; hh++) {
                int qrow = qrow0 + hh * 8;
                #pragma unroll
                for (int j = 0; j < 8; j++) {
                    #pragma unroll
                    for (int c = 0; c < 2; c++) {
                        float v = sacc[j][2 * hh + c] * 0.125f;
                        if (needmask) {
                            int kv = kt * 64 + j * 8 + (lane & 3) * 2 + c;
                            if (kv > qrow) v = -1e30f;
                        }
                        sacc[j][2 * hh + c] = v;
                    }
                }
                float mx = -1e30f;
                #pragma unroll
                for (int j = 0; j < 8; j++)
                    mx = fmaxf(mx, fmaxf(sacc[j][2 * hh], sacc[j][2 * hh + 1]));
                mx = fmaxf(mx, __shfl_xor_sync(0xffffffffu, mx, 1));
                mx = fmaxf(mx, __shfl_xor_sync(0xffffffffu, mx, 2));
                float mn = fmaxf(m2[hh], mx);
                float sum = 0.0f;
                #pragma unroll
                for (int j = 0; j < 8; j++) {
                    float p0 = __expf(sacc[j][2 * hh]     - mn);
                    float p1 = __expf(sacc[j][2 * hh + 1] - mn);
                    sacc[j][2 * hh]     = p0;
                    sacc[j][2 * hh + 1] = p1;
                    sum += p0 + p1;
                }
                sum += __shfl_xor_sync(0xffffffffu, sum, 1);
                sum += __shfl_xor_sync(0xffffffffu, sum, 2);
                float alpha = __expf(m2[hh] - mn);
                m2[hh] = mn;
                l2[hh] = l2[hh] * alpha + sum;
                #pragma unroll
                for (int j = 0; j < 8; j++) {
                    oacc[j][2 * hh]     *= alpha;
                    oacc[j][2 * hh + 1] *= alpha;
                }
            }

            uint32_t pah[4][4], pal[4][4];
            #pragma unroll
            for (int kk = 0; kk < 4; kk++) {
                #pragma unroll
                for (int t = 0; t < 4; t++) {
                    int j  = 2 * kk + (t >> 1);
                    int ci = (t & 1) * 2;
                    float v0 = sacc[j][ci], v1 = sacc[j][ci + 1];
                    __nv_bfloat16 h0 = __float2bfloat16(v0);
                    __nv_bfloat16 h1 = __float2bfloat16(v1);
                    pah[kk][t] = pk2(h0, h1);
                    pal[kk][t] = pk2(__float2bfloat16(v0 - __bfloat162float(h0)),
                                     __float2bfloat16(v1 - __bfloat162float(h1)));
                }
            }

            int r   = lane & 7;
            int mm  = lane >> 3;
            #pragma unroll
            for (int jp = 0; jp < 4; jp++) {
                #pragma unroll
                for (int kk = 0; kk < 4; kk++) {
                    uint32_t off = (uint32_t)((kk * 16 + r + (mm & 1) * 8) * AT_ROWB)
                                 + (uint32_t)((jp * 16 + (mm >> 1) * 8) * 2);
                    uint32_t vhr[4], vlr[4];
                    ldsm4t(vhr, vb_h + off);
                    ldsm4t(vlr, vb_l + off);
                    mma16816(oacc[2 * jp],     pah[kk], vhr[0], vhr[1]);
                    mma16816(oacc[2 * jp + 1], pah[kk], vhr[2], vhr[3]);
                    mma16816(oacc[2 * jp],     pal[kk], vhr[0], vhr[1]);
                    mma16816(oacc[2 * jp + 1], pal[kk], vhr[2], vhr[3]);
                    mma16816(oacc[2 * jp],     pah[kk], vlr[0], vlr[1]);
                    mma16816(oacc[2 * jp + 1], pah[kk], vlr[2], vlr[3]);
                }
            }
        }
        __syncthreads();
    }

    float inv0 = 1.0f / l2[0];
    float inv1 = 1.0f / l2[1];
    size_t obase = (size_t)(b * SEQ) * DIM + h * 64;
    int row1 = q0 + w * 16 + (lane >> 2);
    int colb = (lane & 3) * 2;
    #pragma unroll
    for (int j = 0; j < 8; j++) {
        int col = j * 8 + colb;
        float v0 = oacc[j][0] * inv0;
        float v1 = oacc[j][1] * inv0;
        float v2 = oacc[j][2] * inv1;
        float v3 = oacc[j][3] * inv1;
        __nv_bfloat16 h0 = __float2bfloat16(v0);
        __nv_bfloat16 h1 = __float2bfloat16(v1);
        __nv_bfloat16 h2 = __float2bfloat16(v2);
        __nv_bfloat16 h3 = __float2bfloat16(v3);
        *(__nv_bfloat162*)(oh + obase + (size_t)row1 * DIM + col) = __nv_bfloat162(h0, h1);
        *(__nv_bfloat162*)(oh + obase + (size_t)(row1 + 8) * DIM + col) = __nv_bfloat162(h2, h3);
        *(__nv_bfloat162*)(ol + obase + (size_t)row1 * DIM + col) =
            __nv_bfloat162(__float2bfloat16(v0 - __bfloat162float(h0)),
                           __float2bfloat16(v1 - __bfloat162float(h1)));
        *(__nv_bfloat162*)(ol + obase + (size_t)(row1 + 8) * DIM + col) =
            __nv_bfloat162(__float2bfloat16(v2 - __bfloat162float(h2)),
                           __float2bfloat16(v3 - __bfloat162float(h3)));
    }
}

// ---------------------------------------------------------------------------
// Launch
// ---------------------------------------------------------------------------
extern "C" void kernel_launch(void* const* d_in, const int* in_sizes, int n_in,
                              void* d_out, int out_size)
{
    const float* x      = (const float*)d_in[0];
    const float* W_qkv  = (const float*)d_in[1];
    const float* b_qkv  = (const float*)d_in[2];
    const float* W_o    = (const float*)d_in[3];
    const float* b_o    = (const float*)d_in[4];
    const float* W_fc   = (const float*)d_in[5];
    const float* b_fc   = (const float*)d_in[6];
    const float* W_pr   = (const float*)d_in[7];
    const float* b_pr   = (const float*)d_in[8];
    const float* g1     = (const float*)d_in[9];
    const float* beta1  = (const float*)d_in[10];
    const float* g2     = (const float*)d_in[11];
    const float* beta2  = (const float*)d_in[12];
    float* out = (float*)d_out;

    __nv_bfloat16 *pWqh, *pWql, *pWoh, *pWol, *pWfh, *pWfl, *pWph, *pWpl;
    __nv_bfloat16 *phh, *phl, *pqh, *pql, *path, *patl, *ph2h, *ph2l, *pfch, *pfcl;
    float *px1;
    cudaGetSymbolAddress((void**)&pWqh, g_Wqkv_h);
    cudaGetSymbolAddress((void**)&pWql, g_Wqkv_l);
    cudaGetSymbolAddress((void**)&pWoh, g_Wo_h);
    cudaGetSymbolAddress((void**)&pWol, g_Wo_l);
    cudaGetSymbolAddress((void**)&pWfh, g_Wfc_h);
    cudaGetSymbolAddress((void**)&pWfl, g_Wfc_l);
    cudaGetSymbolAddress((void**)&pWph, g_Wpr_h);
    cudaGetSymbolAddress((void**)&pWpl, g_Wpr_l);
    cudaGetSymbolAddress((void**)&phh,  g_h_h);
    cudaGetSymbolAddress((void**)&phl,  g_h_l);
    cudaGetSymbolAddress((void**)&pqh,  g_qkv_h);
    cudaGetSymbolAddress((void**)&pql,  g_qkv_l);
    cudaGetSymbolAddress((void**)&path, g_att_h);
    cudaGetSymbolAddress((void**)&patl, g_att_l);
    cudaGetSymbolAddress((void**)&px1,  g_x1);
    cudaGetSymbolAddress((void**)&ph2h, g_h2_h);
    cudaGetSymbolAddress((void**)&ph2l, g_h2_l);
    cudaGetSymbolAddress((void**)&pfch, g_fc_h);
    cudaGetSymbolAddress((void**)&pfcl, g_fc_l);

    cudaFuncSetAttribute(attn_mma,
                         cudaFuncAttributeMaxDynamicSharedMemorySize, ATTN_SMEM);
    cudaFuncSetAttribute(gemm_mma<0>,
                         cudaFuncAttributeMaxDynamicSharedMemorySize, GEMM_SMEM);
    cudaFuncSetAttribute(gemm_mma<1>,
                         cudaFuncAttributeMaxDynamicSharedMemorySize, GEMM_SMEM);
    cudaFuncSetAttribute(gemm_mma<2>,
                         cudaFuncAttributeMaxDynamicSharedMemorySize, GEMM_SMEM);
    cudaFuncSetAttribute(gemm_mma<3>,
                         cudaFuncAttributeMaxDynamicSharedMemorySize, GEMM_SMEM);

    // Weight prep (transpose + hi/lo split)
    wtrans_kernel<<<dim3(3072 / 32, 1024 / 32), 256>>>(W_qkv, pWqh, pWql, 1024, 3072);
    wtrans_kernel<<<dim3(1024 / 32, 1024 / 32), 256>>>(W_o,   pWoh, pWol, 1024, 1024);
    wtrans_kernel<<<dim3(4096 / 32, 1024 / 32), 256>>>(W_fc,  pWfh, pWfl, 1024, 4096);
    wtrans_kernel<<<dim3(1024 / 32, 4096 / 32), 256>>>(W_pr,  pWph, pWpl, 4096, 1024);

    // 1. LN1 -> h (hi/lo)
    ln_kernel<<<MROWS, 256>>>(x, g1, beta1, phh, phl);
    // 2. QKV projection -> bf16 hi/lo
    gemm_mma<3><<<dim3(3072 / 256, MROWS / 128), 256, GEMM_SMEM>>>(
        phh, phl, pWqh, pWql, b_qkv, nullptr, nullptr, pqh, pql,
        MROWS, 3 * DIM, DIM);
    // 3. Attention (tensor-core flash) -> att hi/lo
    attn_mma<<<dim3(SEQ / 128, BATCH * NHEAD), 256, ATTN_SMEM>>>(
        pqh, pql, path, patl);
    // 4. Output projection + residual -> x1
    gemm_mma<1><<<dim3(DIM / 256, MROWS / 128), 256, GEMM_SMEM>>>(
        path, patl, pWoh, pWol, b_o, x, px1, nullptr, nullptr,
        MROWS, DIM, DIM);
    // 5. LN2 -> h2 (hi/lo)
    ln_kernel<<<MROWS, 256>>>(px1, g2, beta2, ph2h, ph2l);
    // 6. FC + GELU -> fc (hi/lo)
    gemm_mma<2><<<dim3(4 * DIM / 256, MROWS / 128), 256, GEMM_SMEM>>>(
        ph2h, ph2l, pWfh, pWfl, b_fc, nullptr, nullptr, pfch, pfcl,
        MROWS, 4 * DIM, DIM);
    // 7. Projection + residual -> out
    gemm_mma<1><<<dim3(DIM / 256, MROWS / 128), 256, GEMM_SMEM>>>(
        pfch, pfcl, pWph, pWpl, b_pr, px1, out, nullptr, nullptr,
        MROWS, DIM, 4 * DIM);
}

// round 6
// speedup vs baseline: 3.5809x; 1.4636x over previous
#include <cuda_runtime.h>
#include <cuda_fp16.h>
#include <math.h>
#include <stdint.h>
#include <string.h>

// Problem constants
#define BATCH 2
#define SEQ   2048
#define DIM   1024
#define NHEAD 16
#define HDIM  64
#define MROWS (BATCH * SEQ)   // 4096

// ---------------------------------------------------------------------------
// Scratch (no allocations allowed -> __device__ globals)
// ---------------------------------------------------------------------------
__device__ __half g_Wqkv_h[3072 * 1024];
__device__ __half g_Wqkv_l[3072 * 1024];
__device__ __half g_Wo_h  [1024 * 1024];
__device__ __half g_Wo_l  [1024 * 1024];
__device__ __half g_Wfc_h [4096 * 1024];
__device__ __half g_Wfc_l [4096 * 1024];
__device__ __half g_Wpr_h [1024 * 4096];
__device__ __half g_Wpr_l [1024 * 4096];

__device__ __half g_h  [MROWS * DIM];
__device__ __half g_qkv[MROWS * 3 * DIM];
__device__ __half g_att[MROWS * DIM];
__device__ float  g_x1 [MROWS * DIM];
__device__ __half g_h2 [MROWS * DIM];
__device__ __half g_fc [MROWS * 4 * DIM];

// ---------------------------------------------------------------------------
// PTX helpers (family-common only: cp.async, ldmatrix, mma.sync)
// ---------------------------------------------------------------------------
__device__ __forceinline__ uint32_t smem_u32(const void* p) {
    uint32_t a;
    asm("{ .reg .u64 t; cvta.to.shared.u64 t, %1; cvt.u32.u64 %0, t; }"
        : "=r"(a) : "l"(p));
    return a;
}

__device__ __forceinline__ void cp16(uint32_t dst, const void* src) {
    asm volatile("cp.async.cg.shared.global [%0], [%1], 16;"
                 :: "r"(dst), "l"(src));
}
#define CP_COMMIT() asm volatile("cp.async.commit_group;" ::: "memory")
#define CP_WAIT2()  asm volatile("cp.async.wait_group 2;" ::: "memory")
#define CP_WAIT1()  asm volatile("cp.async.wait_group 1;" ::: "memory")
#define CP_WAIT0()  asm volatile("cp.async.wait_group 0;" ::: "memory")

__device__ __forceinline__ void ldsm4(uint32_t* r, uint32_t a) {
    asm volatile("ldmatrix.sync.aligned.m8n8.x4.shared.b16 {%0,%1,%2,%3}, [%4];"
                 : "=r"(r[0]), "=r"(r[1]), "=r"(r[2]), "=r"(r[3]) : "r"(a));
}
__device__ __forceinline__ void ldsm4t(uint32_t* r, uint32_t a) {
    asm volatile("ldmatrix.sync.aligned.m8n8.x4.trans.shared.b16 {%0,%1,%2,%3}, [%4];"
                 : "=r"(r[0]), "=r"(r[1]), "=r"(r[2]), "=r"(r[3]) : "r"(a));
}

__device__ __forceinline__ void mma16816(float* d, const uint32_t* a,
                                         uint32_t b0, uint32_t b1) {
    asm volatile(
        "mma.sync.aligned.m16n8k16.row.col.f32.f16.f16.f32 "
        "{%0,%1,%2,%3}, {%4,%5,%6,%7}, {%8,%9}, {%0,%1,%2,%3};"
        : "+f"(d[0]), "+f"(d[1]), "+f"(d[2]), "+f"(d[3])
        : "r"(a[0]), "r"(a[1]), "r"(a[2]), "r"(a[3]), "r"(b0), "r"(b1));
}

__device__ __forceinline__ uint32_t pk2h(__half a, __half b) {
    __half2 t(a, b);
    uint32_t r;
    memcpy(&r, &t, 4);
    return r;
}

// ---------------------------------------------------------------------------
// fp16 mma.sync GEMM, asymmetric compensation:
//   A single fp16 [M,K] K-major, B = Bh + Bl fp16 [N,K] K-major (2 passes).
// Block tile 128x256x32, 8 warps (2x4), warp tile 64x64. 3-stage cp.async.
// EPI: 1 = +bias+res -> fp32; 2 = gelu(+bias) -> fp16; 3 = +bias -> fp16
// ---------------------------------------------------------------------------
#define TS 40                        // smem row stride in fp16 elems (80 bytes)
#define TILE_A (128 * TS * 2)        // 10240 bytes (128-row tile)
#define TILE_BB (256 * TS * 2)       // 20480 bytes (256-row tile)
#define STAGE_B (TILE_A + 2 * TILE_BB)       // 51200
#define GEMM_SMEM (3 * STAGE_B)      // 153600

template <int EPI>
__global__ __launch_bounds__(256, 1) void gemm_mma(
    const __half* __restrict__ A,
    const __half* __restrict__ Bh, const __half* __restrict__ Bl,
    const float* __restrict__ bias, const float* __restrict__ res,
    float* __restrict__ Co, __half* __restrict__ Ch,
    int M, int N, int K)
{
    extern __shared__ char sm_raw[];
    uint32_t sb = smem_u32(sm_raw);

    int tid  = threadIdx.x;
    int w    = tid >> 5;
    int lane = tid & 31;
    int wm   = w >> 2;               // 0..1  (64-row group)
    int wn   = w & 3;                // 0..3  (64-col group)
    int n0   = blockIdx.x * 256;
    int m0   = blockIdx.y * 128;

    const __half* srcA = A + (size_t)m0 * K;
    const __half* srcB[2] = { Bh + (size_t)n0 * K, Bl + (size_t)n0 * K };

    float acc[4][8][4];
    #pragma unroll
    for (int i = 0; i < 4; i++)
        #pragma unroll
        for (int j = 0; j < 8; j++)
            #pragma unroll
            for (int q = 0; q < 4; q++) acc[i][j][q] = 0.0f;

    int nch = K >> 5;                // K/32

    // stage loader: A 128 rows + B 2x256 rows, 4 chunks(16B) each = 2560 cp
    auto load_stage = [&](int c, int s) {
        int k0 = c << 5;
        uint32_t stg = sb + s * STAGE_B;
        #pragma unroll
        for (int it = 0; it < 10; it++) {
            int idx = it * 256 + tid;          // 0..2559
            const __half* src;
            uint32_t dst;
            if (idx < 512) {                   // A tile: 128 rows x 4 chunks
                int row   = idx >> 2;
                int chunk = idx & 3;
                src = srcA + (size_t)row * K + k0 + chunk * 8;
                dst = stg + (uint32_t)(row * TS + chunk * 8) * 2;
            } else {                           // B tiles: 2 x 256 rows x 4 chunks
                int idx2  = idx - 512;
                int mat   = idx2 >> 10;        // 0..1
                int row   = (idx2 >> 2) & 255;
                int chunk = idx2 & 3;
                src = srcB[mat] + (size_t)row * K + k0 + chunk * 8;
                dst = stg + TILE_A + mat * TILE_BB
                    + (uint32_t)(row * TS + chunk * 8) * 2;
            }
            cp16(dst, src);
        }
        CP_COMMIT();
    };

    load_stage(0, 0);
    if (nch > 1) load_stage(1, 1);
    if (nch > 2) load_stage(2, 2);

    int arow = wm * 64 + (lane & 15);
    uint32_t a_off = (uint32_t)(arow * TS + (lane >> 4) * 8) * 2;
    int bmat = lane >> 3;                 // 0..3
    int b_h  = bmat & 1;                  // k half
    int b_j  = bmat >> 1;                 // n8 tile within 16-col group
    uint32_t b_off = (uint32_t)((wn * 64 + b_j * 8 + (lane & 7)) * TS + b_h * 8) * 2;

    for (int c = 0; c < nch; c++) {
        int s = c % 3;
        int rem = nch - 1 - c;
        if (rem >= 2) { CP_WAIT2(); }
        else if (rem == 1) { CP_WAIT1(); }
        else { CP_WAIT0(); }
        __syncthreads();

        uint32_t stg = sb + s * STAGE_B;
        uint32_t pA  = stg;
        uint32_t pBh = stg + TILE_A;
        uint32_t pBl = stg + TILE_A + TILE_BB;

        #pragma unroll
        for (int kk = 0; kk < 32; kk += 16) {
            uint32_t kb = (uint32_t)kk * 2;
            uint32_t ah[4][4];
            #pragma unroll
            for (int i = 0; i < 4; i++)
                ldsm4(ah[i], pA + a_off + kb + (uint32_t)i * 16 * TS * 2);
            #pragma unroll
            for (int g = 0; g < 4; g++) {          // 16-col groups
                uint32_t boff = b_off + (uint32_t)g * 16 * TS * 2 + kb;
                uint32_t bh[4], bl[4];
                ldsm4(bh, pBh + boff);
                ldsm4(bl, pBl + boff);
                int j0 = 2 * g, j1 = 2 * g + 1;
                #pragma unroll
                for (int i = 0; i < 4; i++) {
                    mma16816(acc[i][j0], ah[i], bh[0], bh[1]);
                    mma16816(acc[i][j1], ah[i], bh[2], bh[3]);
                    mma16816(acc[i][j0], ah[i], bl[0], bl[1]);
                    mma16816(acc[i][j1], ah[i], bl[2], bl[3]);
                }
            }
        }
        __syncthreads();
        if (c + 3 < nch) load_stage(c + 3, s);
    }

    // Epilogue
    int r0 = m0 + wm * 64 + (lane >> 2);
    int c0 = n0 + wn * 64 + (lane & 3) * 2;
    #pragma unroll
    for (int i = 0; i < 4; i++) {
        int row = r0 + i * 16;
        #pragma unroll
        for (int j = 0; j < 8; j++) {
            int col = c0 + j * 8;
            float b0 = bias[col], b1 = bias[col + 1];
            float v0 = acc[i][j][0] + b0;
            float v1 = acc[i][j][1] + b1;
            float v2 = acc[i][j][2] + b0;
            float v3 = acc[i][j][3] + b1;
            if (EPI == 1) {
                const float* rp0 = res + (size_t)row * N + col;
                const float* rp1 = res + (size_t)(row + 8) * N + col;
                v0 += rp0[0]; v1 += rp0[1];
                v2 += rp1[0]; v3 += rp1[1];
                *(float2*)(Co + (size_t)row * N + col) = make_float2(v0, v1);
                *(float2*)(Co + (size_t)(row + 8) * N + col) = make_float2(v2, v3);
            } else {
                if (EPI == 2) {
                    v0 = 0.5f * v0 * (1.0f + erff(v0 * 0.70710678118654752f));
                    v1 = 0.5f * v1 * (1.0f + erff(v1 * 0.70710678118654752f));
                    v2 = 0.5f * v2 * (1.0f + erff(v2 * 0.70710678118654752f));
                    v3 = 0.5f * v3 * (1.0f + erff(v3 * 0.70710678118654752f));
                }
                *(__half2*)(Ch + (size_t)row * N + col) =
                    __half2(__float2half(v0), __float2half(v1));
                *(__half2*)(Ch + (size_t)(row + 8) * N + col) =
                    __half2(__float2half(v2), __float2half(v3));
            }
        }
    }
}

// ---------------------------------------------------------------------------
// Weight prep: W[K,N] fp32 -> Wt hi/lo fp16 [N,K]
// ---------------------------------------------------------------------------
__global__ __launch_bounds__(256) void wtrans_kernel(
    const float* __restrict__ W, __half* __restrict__ Th,
    __half* __restrict__ Tl, int K, int N)
{
    __shared__ float t[32][33];
    int n0 = blockIdx.x * 32, k0 = blockIdx.y * 32;
    int tx = threadIdx.x & 31, ty = threadIdx.x >> 5;
    #pragma unroll
    for (int i = 0; i < 4; i++) {
        int kr = ty * 4 + i;
        t[kr][tx] = W[(size_t)(k0 + kr) * N + n0 + tx];
    }
    __syncthreads();
    #pragma unroll
    for (int i = 0; i < 4; i++) {
        int nr = ty * 4 + i;
        float v = t[tx][nr];
        size_t o = (size_t)(n0 + nr) * K + k0 + tx;
        __half hv = __float2half(v);
        Th[o] = hv;
        Tl[o] = __float2half(v - __half2float(hv));
    }
}

// ---------------------------------------------------------------------------
// LayerNorm -> fp16 output. One block per row, 256 threads, float4.
// ---------------------------------------------------------------------------
__global__ __launch_bounds__(256) void ln_kernel(
    const float* __restrict__ x, const float* __restrict__ g,
    const float* __restrict__ b, __half* __restrict__ y)
{
    __shared__ float sh[16];
    int row = blockIdx.x;
    int t = threadIdx.x;
    const float4* xr = (const float4*)(x + (size_t)row * DIM);
    float4 v = xr[t];
    float s  = v.x + v.y + v.z + v.w;
    float s2 = v.x*v.x + v.y*v.y + v.z*v.z + v.w*v.w;
    #pragma unroll
    for (int o = 16; o > 0; o >>= 1) {
        s  += __shfl_xor_sync(0xffffffffu, s,  o);
        s2 += __shfl_xor_sync(0xffffffffu, s2, o);
    }
    if ((t & 31) == 0) { sh[t >> 5] = s; sh[8 + (t >> 5)] = s2; }
    __syncthreads();
    if (t < 32) {
        float a  = (t < 8) ? sh[t]     : 0.0f;
        float a2 = (t < 8) ? sh[8 + t] : 0.0f;
        #pragma unroll
        for (int o = 4; o > 0; o >>= 1) {
            a  += __shfl_xor_sync(0xffffffffu, a,  o);
            a2 += __shfl_xor_sync(0xffffffffu, a2, o);
        }
        if (t == 0) { sh[0] = a; sh[1] = a2; }
    }
    __syncthreads();
    float mean = sh[0] * (1.0f / DIM);
    float var  = sh[1] * (1.0f / DIM) - mean * mean;
    float rstd = rsqrtf(var + 1e-5f);
    float4 gg = ((const float4*)g)[t];
    float4 bb = ((const float4*)b)[t];
    float o0 = (v.x - mean) * rstd * gg.x + bb.x;
    float o1 = (v.y - mean) * rstd * gg.y + bb.y;
    float o2 = (v.z - mean) * rstd * gg.z + bb.z;
    float o3 = (v.w - mean) * rstd * gg.w + bb.w;
    size_t o = (size_t)row * DIM + t * 4;
    __half2* hp = (__half2*)(y + o);
    hp[0] = __half2(__float2half(o0), __float2half(o1));
    hp[1] = __half2(__float2half(o2), __float2half(o3));
}

// ---------------------------------------------------------------------------
// Flash attention on fp16 mma.sync, single-precision-pass.
// CTA: 128 queries x one (b,h). 8 warps, 16 q-rows each. kv tiles of 64.
// ---------------------------------------------------------------------------
#define AT_STRIDE 72                 // fp16 elems per smem row (144 B)
#define AT_ROWB   (AT_STRIDE * 2)    // 144
#define AT_TILE   (64 * AT_ROWB)     // 9216
#define AT_STAGE  (2 * AT_TILE)      // 18432 (K, V)
#define ATTN_SMEM (2 * AT_STAGE)     // 36864

__global__ __launch_bounds__(256) void attn_mma(
    const __half* __restrict__ qkv,
    __half* __restrict__ oout)
{
    extern __shared__ char sm_raw[];
    uint32_t sb = smem_u32(sm_raw);

    int tid  = threadIdx.x;
    int w    = tid >> 5;
    int lane = tid & 31;
    int qb   = (int)(gridDim.x - 1 - blockIdx.x);   // long CTAs first
    int bhid = blockIdx.y;
    int b    = bhid >> 4;
    int h    = bhid & 15;
    int q0   = qb * 128;
    const int D3 = 3 * DIM;
    size_t rowbase = (size_t)(b * SEQ) * D3 + h * 64;

    // ---- Load Q into smem (temporarily in stage area) ----
    #pragma unroll
    for (int it = 0; it < 4; it++) {
        int idx = it * 256 + tid;            // 0..1023
        int row = idx >> 3;                  // 0..127
        int c   = idx & 7;
        const __half* src = qkv + rowbase + (size_t)(q0 + row) * D3 + c * 8;
        *(uint4*)(sm_raw + row * AT_ROWB + c * 16) = *(const uint4*)src;
    }
    __syncthreads();

    uint32_t qf[4][4];
    {
        int row = w * 16 + (lane & 15);
        uint32_t boff = (uint32_t)(row * AT_ROWB) + (uint32_t)((lane >> 4) * 16);
        #pragma unroll
        for (int kk = 0; kk < 4; kk++)
            ldsm4(qf[kk], sb + boff + kk * 32);
    }
    __syncthreads();

    float m2[2] = { -1e30f, -1e30f };
    float l2[2] = { 0.0f, 0.0f };
    float oacc[8][4];
    #pragma unroll
    for (int j = 0; j < 8; j++)
        #pragma unroll
        for (int q = 0; q < 4; q++) oacc[j][q] = 0.0f;

    const __half* kv_srcs[2] = { qkv + rowbase + DIM, qkv + rowbase + 2 * DIM };

    auto load_kv = [&](int kt, int s) {
        #pragma unroll
        for (int it = 0; it < 4; it++) {
            int idx = it * 256 + tid;        // 0..1023
            int mat = idx >> 9;              // 0..1 (K, V)
            int rem = idx & 511;
            int row = rem >> 3;              // 0..63
            int c   = rem & 7;
            const __half* src =
                kv_srcs[mat] + (size_t)(kt * 64 + row) * D3 + c * 8;
            cp16(sb + s * AT_STAGE + mat * AT_TILE + row * AT_ROWB + c * 16, src);
        }
        CP_COMMIT();
    };

    int ktmax = 2 * qb + 1;
    load_kv(0, 0);

    int qrow0 = q0 + w * 16 + (lane >> 2);

    for (int kt = 0; kt <= ktmax; kt++) {
        int s = kt & 1;
        if (kt < ktmax) { load_kv(kt + 1, s ^ 1); CP_WAIT1(); }
        else            { CP_WAIT0(); }
        __syncthreads();

        bool active = (kt * 64 <= q0 + w * 16 + 15);
        if (active) {
            uint32_t kb_s = sb + s * AT_STAGE;
            uint32_t vb_s = kb_s + AT_TILE;

            float sacc[8][4];
            #pragma unroll
            for (int j = 0; j < 8; j++)
                #pragma unroll
                for (int q = 0; q < 4; q++) sacc[j][q] = 0.0f;

            int bm   = lane >> 3;
            int bkh  = bm & 1;
            int bjj  = bm >> 1;
            int brow = (lane & 7) + bjj * 8;
            #pragma unroll
            for (int jp = 0; jp < 4; jp++) {
                #pragma unroll
                for (int kk = 0; kk < 4; kk++) {
                    uint32_t off = (uint32_t)((jp * 16 + brow) * AT_ROWB)
                                 + (uint32_t)((bkh * 8 + kk * 16) * 2);
                    uint32_t khr[4];
                    ldsm4(khr, kb_s + off);
                    mma16816(sacc[2 * jp],     qf[kk], khr[0], khr[1]);
                    mma16816(sacc[2 * jp + 1], qf[kk], khr[2], khr[3]);
                }
            }

            bool needmask = (kt * 64 + 63 > q0 + w * 16);
            #pragma unroll
            for (int hh = 0; hh < 2; hh++) {
                int qrow = qrow0 + hh * 8;
                #pragma unroll
                for (int j = 0; j < 8; j++) {
                    #pragma unroll
                    for (int c = 0; c < 2; c++) {
                        float v = sacc[j][2 * hh + c] * 0.125f;
                        if (needmask) {
                            int kv = kt * 64 + j * 8 + (lane & 3) * 2 + c;
                            if (kv > qrow) v = -1e30f;
                        }
                        sacc[j][2 * hh + c] = v;
                    }
                }
                float mx = -1e30f;
                #pragma unroll
                for (int j = 0; j < 8; j++)
                    mx = fmaxf(mx, fmaxf(sacc[j][2 * hh], sacc[j][2 * hh + 1]));
                mx = fmaxf(mx, __shfl_xor_sync(0xffffffffu, mx, 1));
                mx = fmaxf(mx, __shfl_xor_sync(0xffffffffu, mx, 2));
                float mn = fmaxf(m2[hh], mx);
                float sum = 0.0f;
                #pragma unroll
                for (int j = 0; j < 8; j++) {
                    float p0 = __expf(sacc[j][2 * hh]     - mn);
                    float p1 = __expf(sacc[j][2 * hh + 1] - mn);
                    sacc[j][2 * hh]     = p0;
                    sacc[j][2 * hh + 1] = p1;
                    sum += p0 + p1;
                }
                sum += __shfl_xor_sync(0xffffffffu, sum, 1);
                sum += __shfl_xor_sync(0xffffffffu, sum, 2);
                float alpha = __expf(m2[hh] - mn);
                m2[hh] = mn;
                l2[hh] = l2[hh] * alpha + sum;
                #pragma unroll
                for (int j = 0; j < 8; j++) {
                    oacc[j][2 * hh]     *= alpha;
                    oacc[j][2 * hh + 1] *= alpha;
                }
            }

            uint32_t pah[4][4];
            #pragma unroll
            for (int kk = 0; kk < 4; kk++) {
                #pragma unroll
                for (int t = 0; t < 4; t++) {
                    int j  = 2 * kk + (t >> 1);
                    int ci = (t & 1) * 2;
                    pah[kk][t] = pk2h(__float2half(sacc[j][ci]),
                                      __float2half(sacc[j][ci + 1]));
                }
            }

            int r   = lane & 7;
            int mm  = lane >> 3;
            #pragma unroll
            for (int jp = 0; jp < 4; jp++) {
                #pragma unroll
                for (int kk = 0; kk < 4; kk++) {
                    uint32_t off = (uint32_t)((kk * 16 + r + (mm & 1) * 8) * AT_ROWB)
                                 + (uint32_t)((jp * 16 + (mm >> 1) * 8) * 2);
                    uint32_t vhr[4];
                    ldsm4t(vhr, vb_s + off);
                    mma16816(oacc[2 * jp],     pah[kk], vhr[0], vhr[1]);
                    mma16816(oacc[2 * jp + 1], pah[kk], vhr[2], vhr[3]);
                }
            }
        }
        __syncthreads();
    }

    float inv0 = 1.0f / l2[0];
    float inv1 = 1.0f / l2[1];
    size_t obase = (size_t)(b * SEQ) * DIM + h * 64;
    int row1 = q0 + w * 16 + (lane >> 2);
    int colb = (lane & 3) * 2;
    #pragma unroll
    for (int j = 0; j < 8; j++) {
        int col = j * 8 + colb;
        *(__half2*)(oout + obase + (size_t)row1 * DIM + col) =
            __half2(__float2half(oacc[j][0] * inv0), __float2half(oacc[j][1] * inv0));
        *(__half2*)(oout + obase + (size_t)(row1 + 8) * DIM + col) =
            __half2(__float2half(oacc[j][2] * inv1), __float2half(oacc[j][3] * inv1));
    }
}

// ---------------------------------------------------------------------------
// Launch
// ---------------------------------------------------------------------------
extern "C" void kernel_launch(void* const* d_in, const int* in_sizes, int n_in,
                              void* d_out, int out_size)
{
    const float* x      = (const float*)d_in[0];
    const float* W_qkv  = (const float*)d_in[1];
    const float* b_qkv  = (const float*)d_in[2];
    const float* W_o    = (const float*)d_in[3];
    const float* b_o    = (const float*)d_in[4];
    const float* W_fc   = (const float*)d_in[5];
    const float* b_fc   = (const float*)d_in[6];
    const float* W_pr   = (const float*)d_in[7];
    const float* b_pr   = (const float*)d_in[8];
    const float* g1     = (const float*)d_in[9];
    const float* beta1  = (const float*)d_in[10];
    const float* g2     = (const float*)d_in[11];
    const float* beta2  = (const float*)d_in[12];
    float* out = (float*)d_out;

    __half *pWqh, *pWql, *pWoh, *pWol, *pWfh, *pWfl, *pWph, *pWpl;
    __half *ph, *pq, *pat, *ph2, *pfc;
    float *px1;
    cudaGetSymbolAddress((void**)&pWqh, g_Wqkv_h);
    cudaGetSymbolAddress((void**)&pWql, g_Wqkv_l);
    cudaGetSymbolAddress((void**)&pWoh, g_Wo_h);
    cudaGetSymbolAddress((void**)&pWol, g_Wo_l);
    cudaGetSymbolAddress((void**)&pWfh, g_Wfc_h);
    cudaGetSymbolAddress((void**)&pWfl, g_Wfc_l);
    cudaGetSymbolAddress((void**)&pWph, g_Wpr_h);
    cudaGetSymbolAddress((void**)&pWpl, g_Wpr_l);
    cudaGetSymbolAddress((void**)&ph,   g_h);
    cudaGetSymbolAddress((void**)&pq,   g_qkv);
    cudaGetSymbolAddress((void**)&pat,  g_att);
    cudaGetSymbolAddress((void**)&px1,  g_x1);
    cudaGetSymbolAddress((void**)&ph2,  g_h2);
    cudaGetSymbolAddress((void**)&pfc,  g_fc);

    cudaFuncSetAttribute(attn_mma,
                         cudaFuncAttributeMaxDynamicSharedMemorySize, ATTN_SMEM);
    cudaFuncSetAttribute(gemm_mma<1>,
                         cudaFuncAttributeMaxDynamicSharedMemorySize, GEMM_SMEM);
    cudaFuncSetAttribute(gemm_mma<2>,
                         cudaFuncAttributeMaxDynamicSharedMemorySize, GEMM_SMEM);
    cudaFuncSetAttribute(gemm_mma<3>,
                         cudaFuncAttributeMaxDynamicSharedMemorySize, GEMM_SMEM);

    // Weight prep (transpose + hi/lo split)
    wtrans_kernel<<<dim3(3072 / 32, 1024 / 32), 256>>>(W_qkv, pWqh, pWql, 1024, 3072);
    wtrans_kernel<<<dim3(1024 / 32, 1024 / 32), 256>>>(W_o,   pWoh, pWol, 1024, 1024);
    wtrans_kernel<<<dim3(4096 / 32, 1024 / 32), 256>>>(W_fc,  pWfh, pWfl, 1024, 4096);
    wtrans_kernel<<<dim3(1024 / 32, 4096 / 32), 256>>>(W_pr,  pWph, pWpl, 4096, 1024);

    // 1. LN1 -> h (fp16)
    ln_kernel<<<MROWS, 256>>>(x, g1, beta1, ph);
    // 2. QKV projection -> fp16
    gemm_mma<3><<<dim3(3072 / 256, MROWS / 128), 256, GEMM_SMEM>>>(
        ph, pWqh, pWql, b_qkv, nullptr, nullptr, pq, MROWS, 3 * DIM, DIM);
    // 3. Attention (tensor-core flash) -> att fp16
    attn_mma<<<dim3(SEQ / 128, BATCH * NHEAD), 256, ATTN_SMEM>>>(pq, pat);
    // 4. Output projection + residual -> x1 (fp32)
    gemm_mma<1><<<dim3(DIM / 256, MROWS / 128), 256, GEMM_SMEM>>>(
        pat, pWoh, pWol, b_o, x, px1, nullptr, MROWS, DIM, DIM);
    // 5. LN2 -> h2 (fp16)
    ln_kernel<<<MROWS, 256>>>(px1, g2, beta2, ph2);
    // 6. FC + GELU -> fc (fp16)
    gemm_mma<2><<<dim3(4 * DIM / 256, MROWS / 128), 256, GEMM_SMEM>>>(
        ph2, pWfh, pWfl, b_fc, nullptr, nullptr, pfc, MROWS, 4 * DIM, DIM);
    // 7. Projection + residual -> out (fp32)
    gemm_mma<1><<<dim3(DIM / 256, MROWS / 128), 256, GEMM_SMEM>>>(
        pfc, pWph, pWpl, b_pr, px1, out, nullptr, MROWS, DIM, 4 * DIM);
}

// round 7
// speedup vs baseline: 5.2897x; 1.4772x over previous
#include <cuda_runtime.h>
#include <cuda_fp16.h>
#include <math.h>
#include <stdint.h>
#include <string.h>

// Problem constants
#define BATCH 2
#define SEQ   2048
#define DIM   1024
#define NHEAD 16
#define HDIM  64
#define MROWS (BATCH * SEQ)   // 4096

// ---------------------------------------------------------------------------
// Scratch (no allocations allowed -> __device__ globals)
// ---------------------------------------------------------------------------
__device__ __half g_Wqkv[3072 * 1024];
__device__ __half g_Wo  [1024 * 1024];
__device__ __half g_Wfc [4096 * 1024];
__device__ __half g_Wpr [1024 * 4096];

__device__ __half g_h  [MROWS * DIM];
__device__ __half g_qkv[MROWS * 3 * DIM];
__device__ __half g_att[MROWS * DIM];
__device__ float  g_x1 [MROWS * DIM];
__device__ __half g_h2 [MROWS * DIM];
__device__ __half g_fc [MROWS * 4 * DIM];

// ---------------------------------------------------------------------------
// PTX helpers (family-common only: cp.async, ldmatrix, mma.sync)
// ---------------------------------------------------------------------------
__device__ __forceinline__ uint32_t smem_u32(const void* p) {
    uint32_t a;
    asm("{ .reg .u64 t; cvta.to.shared.u64 t, %1; cvt.u32.u64 %0, t; }"
        : "=r"(a) : "l"(p));
    return a;
}

__device__ __forceinline__ void cp16(uint32_t dst, const void* src) {
    asm volatile("cp.async.cg.shared.global [%0], [%1], 16;"
                 :: "r"(dst), "l"(src));
}
#define CP_COMMIT() asm volatile("cp.async.commit_group;" ::: "memory")
#define CP_WAIT2()  asm volatile("cp.async.wait_group 2;" ::: "memory")
#define CP_WAIT1()  asm volatile("cp.async.wait_group 1;" ::: "memory")
#define CP_WAIT0()  asm volatile("cp.async.wait_group 0;" ::: "memory")

__device__ __forceinline__ void ldsm4(uint32_t* r, uint32_t a) {
    asm volatile("ldmatrix.sync.aligned.m8n8.x4.shared.b16 {%0,%1,%2,%3}, [%4];"
                 : "=r"(r[0]), "=r"(r[1]), "=r"(r[2]), "=r"(r[3]) : "r"(a));
}
__device__ __forceinline__ void ldsm4t(uint32_t* r, uint32_t a) {
    asm volatile("ldmatrix.sync.aligned.m8n8.x4.trans.shared.b16 {%0,%1,%2,%3}, [%4];"
                 : "=r"(r[0]), "=r"(r[1]), "=r"(r[2]), "=r"(r[3]) : "r"(a));
}

__device__ __forceinline__ void mma16816(float* d, const uint32_t* a,
                                         uint32_t b0, uint32_t b1) {
    asm volatile(
        "mma.sync.aligned.m16n8k16.row.col.f32.f16.f16.f32 "
        "{%0,%1,%2,%3}, {%4,%5,%6,%7}, {%8,%9}, {%0,%1,%2,%3};"
        : "+f"(d[0]), "+f"(d[1]), "+f"(d[2]), "+f"(d[3])
        : "r"(a[0]), "r"(a[1]), "r"(a[2]), "r"(a[3]), "r"(b0), "r"(b1));
}

__device__ __forceinline__ uint32_t pk2h(__half a, __half b) {
    __half2 t(a, b);
    uint32_t r;
    memcpy(&r, &t, 4);
    return r;
}

// ---------------------------------------------------------------------------
// fp16 mma.sync GEMM, single pass:
//   A fp16 [M,K] K-major, B fp16 [N,K] K-major.
// Block tile 128x256x32, 8 warps (2x4), warp tile 64x64. 3-stage cp.async.
// EPI: 1 = +bias+res -> fp32; 2 = gelu(+bias) -> fp16; 3 = +bias -> fp16
// ---------------------------------------------------------------------------
#define TS 40                        // smem row stride in fp16 elems (80 bytes)
#define TILE_A (128 * TS * 2)        // 10240 bytes (128-row tile)
#define TILE_BB (256 * TS * 2)       // 20480 bytes (256-row tile)
#define STAGE_B (TILE_A + TILE_BB)   // 30720
#define GEMM_SMEM (3 * STAGE_B)      // 92160

template <int EPI>
__global__ __launch_bounds__(256, 1) void gemm_mma(
    const __half* __restrict__ A, const __half* __restrict__ B,
    const float* __restrict__ bias, const float* __restrict__ res,
    float* __restrict__ Co, __half* __restrict__ Ch,
    int M, int N, int K)
{
    extern __shared__ char sm_raw[];
    uint32_t sb = smem_u32(sm_raw);

    int tid  = threadIdx.x;
    int w    = tid >> 5;
    int lane = tid & 31;
    int wm   = w >> 2;               // 0..1  (64-row group)
    int wn   = w & 3;                // 0..3  (64-col group)
    int n0   = blockIdx.x * 256;
    int m0   = blockIdx.y * 128;

    const __half* srcA = A + (size_t)m0 * K;
    const __half* srcB = B + (size_t)n0 * K;

    float acc[4][8][4];
    #pragma unroll
    for (int i = 0; i < 4; i++)
        #pragma unroll
        for (int j = 0; j < 8; j++)
            #pragma unroll
            for (int q = 0; q < 4; q++) acc[i][j][q] = 0.0f;

    int nch = K >> 5;                // K/32

    // stage loader: A 128 rows + B 256 rows, 4 chunks(16B) each = 1536 cp
    auto load_stage = [&](int c, int s) {
        int k0 = c << 5;
        uint32_t stg = sb + s * STAGE_B;
        #pragma unroll
        for (int it = 0; it < 6; it++) {
            int idx = it * 256 + tid;          // 0..1535
            const __half* src;
            uint32_t dst;
            if (idx < 512) {                   // A tile: 128 rows x 4 chunks
                int row   = idx >> 2;
                int chunk = idx & 3;
                src = srcA + (size_t)row * K + k0 + chunk * 8;
                dst = stg + (uint32_t)(row * TS + chunk * 8) * 2;
            } else {                           // B tile: 256 rows x 4 chunks
                int idx2  = idx - 512;
                int row   = idx2 >> 2;
                int chunk = idx2 & 3;
                src = srcB + (size_t)row * K + k0 + chunk * 8;
                dst = stg + TILE_A + (uint32_t)(row * TS + chunk * 8) * 2;
            }
            cp16(dst, src);
        }
        CP_COMMIT();
    };

    load_stage(0, 0);
    if (nch > 1) load_stage(1, 1);
    if (nch > 2) load_stage(2, 2);

    int arow = wm * 64 + (lane & 15);
    uint32_t a_off = (uint32_t)(arow * TS + (lane >> 4) * 8) * 2;
    int bmat = lane >> 3;                 // 0..3
    int b_h  = bmat & 1;                  // k half
    int b_j  = bmat >> 1;                 // n8 tile within 16-col group
    uint32_t b_off = (uint32_t)((wn * 64 + b_j * 8 + (lane & 7)) * TS + b_h * 8) * 2;

    for (int c = 0; c < nch; c++) {
        int s = c % 3;
        int rem = nch - 1 - c;
        if (rem >= 2) { CP_WAIT2(); }
        else if (rem == 1) { CP_WAIT1(); }
        else { CP_WAIT0(); }
        __syncthreads();

        uint32_t stg = sb + s * STAGE_B;
        uint32_t pA = stg;
        uint32_t pB = stg + TILE_A;

        #pragma unroll
        for (int kk = 0; kk < 32; kk += 16) {
            uint32_t kb = (uint32_t)kk * 2;
            uint32_t ah[4][4];
            #pragma unroll
            for (int i = 0; i < 4; i++)
                ldsm4(ah[i], pA + a_off + kb + (uint32_t)i * 16 * TS * 2);
            #pragma unroll
            for (int g = 0; g < 4; g++) {          // 16-col groups
                uint32_t boff = b_off + (uint32_t)g * 16 * TS * 2 + kb;
                uint32_t bh[4];
                ldsm4(bh, pB + boff);
                int j0 = 2 * g, j1 = 2 * g + 1;
                #pragma unroll
                for (int i = 0; i < 4; i++) {
                    mma16816(acc[i][j0], ah[i], bh[0], bh[1]);
                    mma16816(acc[i][j1], ah[i], bh[2], bh[3]);
                }
            }
        }
        __syncthreads();
        if (c + 3 < nch) load_stage(c + 3, s);
    }

    // Epilogue
    int r0 = m0 + wm * 64 + (lane >> 2);
    int c0 = n0 + wn * 64 + (lane & 3) * 2;
    #pragma unroll
    for (int i = 0; i < 4; i++) {
        int row = r0 + i * 16;
        #pragma unroll
        for (int j = 0; j < 8; j++) {
            int col = c0 + j * 8;
            float b0 = bias[col], b1 = bias[col + 1];
            float v0 = acc[i][j][0] + b0;
            float v1 = acc[i][j][1] + b1;
            float v2 = acc[i][j][2] + b0;
            float v3 = acc[i][j][3] + b1;
            if (EPI == 1) {
                const float* rp0 = res + (size_t)row * N + col;
                const float* rp1 = res + (size_t)(row + 8) * N + col;
                v0 += rp0[0]; v1 += rp0[1];
                v2 += rp1[0]; v3 += rp1[1];
                *(float2*)(Co + (size_t)row * N + col) = make_float2(v0, v1);
                *(float2*)(Co + (size_t)(row + 8) * N + col) = make_float2(v2, v3);
            } else {
                if (EPI == 2) {
                    v0 = 0.5f * v0 * (1.0f + erff(v0 * 0.70710678118654752f));
                    v1 = 0.5f * v1 * (1.0f + erff(v1 * 0.70710678118654752f));
                    v2 = 0.5f * v2 * (1.0f + erff(v2 * 0.70710678118654752f));
                    v3 = 0.5f * v3 * (1.0f + erff(v3 * 0.70710678118654752f));
                }
                *(__half2*)(Ch + (size_t)row * N + col) =
                    __half2(__float2half(v0), __float2half(v1));
                *(__half2*)(Ch + (size_t)(row + 8) * N + col) =
                    __half2(__float2half(v2), __float2half(v3));
            }
        }
    }
}

// ---------------------------------------------------------------------------
// Weight prep: W[K,N] fp32 -> Wt fp16 [N,K]
// ---------------------------------------------------------------------------
__global__ __launch_bounds__(256) void wtrans_kernel(
    const float* __restrict__ W, __half* __restrict__ T, int K, int N)
{
    __shared__ float t[32][33];
    int n0 = blockIdx.x * 32, k0 = blockIdx.y * 32;
    int tx = threadIdx.x & 31, ty = threadIdx.x >> 5;
    #pragma unroll
    for (int i = 0; i < 4; i++) {
        int kr = ty * 4 + i;
        t[kr][tx] = W[(size_t)(k0 + kr) * N + n0 + tx];
    }
    __syncthreads();
    #pragma unroll
    for (int i = 0; i < 4; i++) {
        int nr = ty * 4 + i;
        T[(size_t)(n0 + nr) * K + k0 + tx] = __float2half(t[tx][nr]);
    }
}

// ---------------------------------------------------------------------------
// LayerNorm -> fp16 output. One block per row, 256 threads, float4.
// ---------------------------------------------------------------------------
__global__ __launch_bounds__(256) void ln_kernel(
    const float* __restrict__ x, const float* __restrict__ g,
    const float* __restrict__ b, __half* __restrict__ y)
{
    __shared__ float sh[16];
    int row = blockIdx.x;
    int t = threadIdx.x;
    const float4* xr = (const float4*)(x + (size_t)row * DIM);
    float4 v = xr[t];
    float s  = v.x + v.y + v.z + v.w;
    float s2 = v.x*v.x + v.y*v.y + v.z*v.z + v.w*v.w;
    #pragma unroll
    for (int o = 16; o > 0; o >>= 1) {
        s  += __shfl_xor_sync(0xffffffffu, s,  o);
        s2 += __shfl_xor_sync(0xffffffffu, s2, o);
    }
    if ((t & 31) == 0) { sh[t >> 5] = s; sh[8 + (t >> 5)] = s2; }
    __syncthreads();
    if (t < 32) {
        float a  = (t < 8) ? sh[t]     : 0.0f;
        float a2 = (t < 8) ? sh[8 + t] : 0.0f;
        #pragma unroll
        for (int o = 4; o > 0; o >>= 1) {
            a  += __shfl_xor_sync(0xffffffffu, a,  o);
            a2 += __shfl_xor_sync(0xffffffffu, a2, o);
        }
        if (t == 0) { sh[0] = a; sh[1] = a2; }
    }
    __syncthreads();
    float mean = sh[0] * (1.0f / DIM);
    float var  = sh[1] * (1.0f / DIM) - mean * mean;
    float rstd = rsqrtf(var + 1e-5f);
    float4 gg = ((const float4*)g)[t];
    float4 bb = ((const float4*)b)[t];
    float o0 = (v.x - mean) * rstd * gg.x + bb.x;
    float o1 = (v.y - mean) * rstd * gg.y + bb.y;
    float o2 = (v.z - mean) * rstd * gg.z + bb.z;
    float o3 = (v.w - mean) * rstd * gg.w + bb.w;
    size_t o = (size_t)row * DIM + t * 4;
    __half2* hp = (__half2*)(y + o);
    hp[0] = __half2(__float2half(o0), __float2half(o1));
    hp[1] = __half2(__float2half(o2), __float2half(o3));
}

// ---------------------------------------------------------------------------
// Flash attention on fp16 mma.sync, single-precision-pass.
// CTA: 128 queries x one (b,h). 8 warps, 16 q-rows each. kv tiles of 64.
// ---------------------------------------------------------------------------
#define AT_STRIDE 72                 // fp16 elems per smem row (144 B)
#define AT_ROWB   (AT_STRIDE * 2)    // 144
#define AT_TILE   (64 * AT_ROWB)     // 9216
#define AT_STAGE  (2 * AT_TILE)      // 18432 (K, V)
#define ATTN_SMEM (2 * AT_STAGE)     // 36864

__global__ __launch_bounds__(256) void attn_mma(
    const __half* __restrict__ qkv,
    __half* __restrict__ oout)
{
    extern __shared__ char sm_raw[];
    uint32_t sb = smem_u32(sm_raw);

    int tid  = threadIdx.x;
    int w    = tid >> 5;
    int lane = tid & 31;
    int qb   = (int)(gridDim.x - 1 - blockIdx.x);   // long CTAs first
    int bhid = blockIdx.y;
    int b    = bhid >> 4;
    int h    = bhid & 15;
    int q0   = qb * 128;
    const int D3 = 3 * DIM;
    size_t rowbase = (size_t)(b * SEQ) * D3 + h * 64;

    // ---- Load Q into smem (temporarily in stage area) ----
    #pragma unroll
    for (int it = 0; it < 4; it++) {
        int idx = it * 256 + tid;            // 0..1023
        int row = idx >> 3;                  // 0..127
        int c   = idx & 7;
        const __half* src = qkv + rowbase + (size_t)(q0 + row) * D3 + c * 8;
        *(uint4*)(sm_raw + row * AT_ROWB + c * 16) = *(const uint4*)src;
    }
    __syncthreads();

    uint32_t qf[4][4];
    {
        int row = w * 16 + (lane & 15);
        uint32_t boff = (uint32_t)(row * AT_ROWB) + (uint32_t)((lane >> 4) * 16);
        #pragma unroll
        for (int kk = 0; kk < 4; kk++)
            ldsm4(qf[kk], sb + boff + kk * 32);
    }
    __syncthreads();

    float m2[2] = { -1e30f, -1e30f };
    float l2[2] = { 0.0f, 0.0f };
    float oacc[8][4];
    #pragma unroll
    for (int j = 0; j < 8; j++)
        #pragma unroll
        for (int q = 0; q < 4; q++) oacc[j][q] = 0.0f;

    const __half* kv_srcs[2] = { qkv + rowbase + DIM, qkv + rowbase + 2 * DIM };

    auto load_kv = [&](int kt, int s) {
        #pragma unroll
        for (int it = 0; it < 4; it++) {
            int idx = it * 256 + tid;        // 0..1023
            int mat = idx >> 9;              // 0..1 (K, V)
            int rem = idx & 511;
            int row = rem >> 3;              // 0..63
            int c   = rem & 7;
            const __half* src =
                kv_srcs[mat] + (size_t)(kt * 64 + row) * D3 + c * 8;
            cp16(sb + s * AT_STAGE + mat * AT_TILE + row * AT_ROWB + c * 16, src);
        }
        CP_COMMIT();
    };

    int ktmax = 2 * qb + 1;
    load_kv(0, 0);

    int qrow0 = q0 + w * 16 + (lane >> 2);

    for (int kt = 0; kt <= ktmax; kt++) {
        int s = kt & 1;
        if (kt < ktmax) { load_kv(kt + 1, s ^ 1); CP_WAIT1(); }
        else            { CP_WAIT0(); }
        __syncthreads();

        bool active = (kt * 64 <= q0 + w * 16 + 15);
        if (active) {
            uint32_t kb_s = sb + s * AT_STAGE;
            uint32_t vb_s = kb_s + AT_TILE;

            float sacc[8][4];
            #pragma unroll
            for (int j = 0; j < 8; j++)
                #pragma unroll
                for (int q = 0; q < 4; q++) sacc[j][q] = 0.0f;

            int bm   = lane >> 3;
            int bkh  = bm & 1;
            int bjj  = bm >> 1;
            int brow = (lane & 7) + bjj * 8;
            #pragma unroll
            for (int jp = 0; jp < 4; jp++) {
                #pragma unroll
                for (int kk = 0; kk < 4; kk++) {
                    uint32_t off = (uint32_t)((jp * 16 + brow) * AT_ROWB)
                                 + (uint32_t)((bkh * 8 + kk * 16) * 2);
                    uint32_t khr[4];
                    ldsm4(khr, kb_s + off);
                    mma16816(sacc[2 * jp],     qf[kk], khr[0], khr[1]);
                    mma16816(sacc[2 * jp + 1], qf[kk], khr[2], khr[3]);
                }
            }

            bool needmask = (kt * 64 + 63 > q0 + w * 16);
            #pragma unroll
            for (int hh = 0; hh < 2; hh++) {
                int qrow = qrow0 + hh * 8;
                #pragma unroll
                for (int j = 0; j < 8; j++) {
                    #pragma unroll
                    for (int c = 0; c < 2; c++) {
                        float v = sacc[j][2 * hh + c] * 0.125f;
                        if (needmask) {
                            int kv = kt * 64 + j * 8 + (lane & 3) * 2 + c;
                            if (kv > qrow) v = -1e30f;
                        }
                        sacc[j][2 * hh + c] = v;
                    }
                }
                float mx = -1e30f;
                #pragma unroll
                for (int j = 0; j < 8; j++)
                    mx = fmaxf(mx, fmaxf(sacc[j][2 * hh], sacc[j][2 * hh + 1]));
                mx = fmaxf(mx, __shfl_xor_sync(0xffffffffu, mx, 1));
                mx = fmaxf(mx, __shfl_xor_sync(0xffffffffu, mx, 2));
                float mn = fmaxf(m2[hh], mx);
                float sum = 0.0f;
                #pragma unroll
                for (int j = 0; j < 8; j++) {
                    float p0 = __expf(sacc[j][2 * hh]     - mn);
                    float p1 = __expf(sacc[j][2 * hh + 1] - mn);
                    sacc[j][2 * hh]     = p0;
                    sacc[j][2 * hh + 1] = p1;
                    sum += p0 + p1;
                }
                sum += __shfl_xor_sync(0xffffffffu, sum, 1);
                sum += __shfl_xor_sync(0xffffffffu, sum, 2);
                float alpha = __expf(m2[hh] - mn);
                m2[hh] = mn;
                l2[hh] = l2[hh] * alpha + sum;
                #pragma unroll
                for (int j = 0; j < 8; j++) {
                    oacc[j][2 * hh]     *= alpha;
                    oacc[j][2 * hh + 1] *= alpha;
                }
            }

            uint32_t pah[4][4];
            #pragma unroll
            for (int kk = 0; kk < 4; kk++) {
                #pragma unroll
                for (int t = 0; t < 4; t++) {
                    int j  = 2 * kk + (t >> 1);
                    int ci = (t & 1) * 2;
                    pah[kk][t] = pk2h(__float2half(sacc[j][ci]),
                                      __float2half(sacc[j][ci + 1]));
                }
            }

            int r   = lane & 7;
            int mm  = lane >> 3;
            #pragma unroll
            for (int jp = 0; jp < 4; jp++) {
                #pragma unroll
                for (int kk = 0; kk < 4; kk++) {
                    uint32_t off = (uint32_t)((kk * 16 + r + (mm & 1) * 8) * AT_ROWB)
                                 + (uint32_t)((jp * 16 + (mm >> 1) * 8) * 2);
                    uint32_t vhr[4];
                    ldsm4t(vhr, vb_s + off);
                    mma16816(oacc[2 * jp],     pah[kk], vhr[0], vhr[1]);
                    mma16816(oacc[2 * jp + 1], pah[kk], vhr[2], vhr[3]);
                }
            }
        }
        __syncthreads();
    }

    float inv0 = 1.0f / l2[0];
    float inv1 = 1.0f / l2[1];
    size_t obase = (size_t)(b * SEQ) * DIM + h * 64;
    int row1 = q0 + w * 16 + (lane >> 2);
    int colb = (lane & 3) * 2;
    #pragma unroll
    for (int j = 0; j < 8; j++) {
        int col = j * 8 + colb;
        *(__half2*)(oout + obase + (size_t)row1 * DIM + col) =
            __half2(__float2half(oacc[j][0] * inv0), __float2half(oacc[j][1] * inv0));
        *(__half2*)(oout + obase + (size_t)(row1 + 8) * DIM + col) =
            __half2(__float2half(oacc[j][2] * inv1), __float2half(oacc[j][3] * inv1));
    }
}

// ---------------------------------------------------------------------------
// Launch
// ---------------------------------------------------------------------------
extern "C" void kernel_launch(void* const* d_in, const int* in_sizes, int n_in,
                              void* d_out, int out_size)
{
    const float* x      = (const float*)d_in[0];
    const float* W_qkv  = (const float*)d_in[1];
    const float* b_qkv  = (const float*)d_in[2];
    const float* W_o    = (const float*)d_in[3];
    const float* b_o    = (const float*)d_in[4];
    const float* W_fc   = (const float*)d_in[5];
    const float* b_fc   = (const float*)d_in[6];
    const float* W_pr   = (const float*)d_in[7];
    const float* b_pr   = (const float*)d_in[8];
    const float* g1     = (const float*)d_in[9];
    const float* beta1  = (const float*)d_in[10];
    const float* g2     = (const float*)d_in[11];
    const float* beta2  = (const float*)d_in[12];
    float* out = (float*)d_out;

    __half *pWq, *pWo, *pWf, *pWp;
    __half *ph, *pq, *pat, *ph2, *pfc;
    float *px1;
    cudaGetSymbolAddress((void**)&pWq,  g_Wqkv);
    cudaGetSymbolAddress((void**)&pWo,  g_Wo);
    cudaGetSymbolAddress((void**)&pWf,  g_Wfc);
    cudaGetSymbolAddress((void**)&pWp,  g_Wpr);
    cudaGetSymbolAddress((void**)&ph,   g_h);
    cudaGetSymbolAddress((void**)&pq,   g_qkv);
    cudaGetSymbolAddress((void**)&pat,  g_att);
    cudaGetSymbolAddress((void**)&px1,  g_x1);
    cudaGetSymbolAddress((void**)&ph2,  g_h2);
    cudaGetSymbolAddress((void**)&pfc,  g_fc);

    cudaFuncSetAttribute(attn_mma,
                         cudaFuncAttributeMaxDynamicSharedMemorySize, ATTN_SMEM);
    cudaFuncSetAttribute(gemm_mma<1>,
                         cudaFuncAttributeMaxDynamicSharedMemorySize, GEMM_SMEM);
    cudaFuncSetAttribute(gemm_mma<2>,
                         cudaFuncAttributeMaxDynamicSharedMemorySize, GEMM_SMEM);
    cudaFuncSetAttribute(gemm_mma<3>,
                         cudaFuncAttributeMaxDynamicSharedMemorySize, GEMM_SMEM);

    // Weight prep (transpose + fp16 convert)
    wtrans_kernel<<<dim3(3072 / 32, 1024 / 32), 256>>>(W_qkv, pWq, 1024, 3072);
    wtrans_kernel<<<dim3(1024 / 32, 1024 / 32), 256>>>(W_o,   pWo, 1024, 1024);
    wtrans_kernel<<<dim3(4096 / 32, 1024 / 32), 256>>>(W_fc,  pWf, 1024, 4096);
    wtrans_kernel<<<dim3(1024 / 32, 4096 / 32), 256>>>(W_pr,  pWp, 4096, 1024);

    // 1. LN1 -> h (fp16)
    ln_kernel<<<MROWS, 256>>>(x, g1, beta1, ph);
    // 2. QKV projection -> fp16
    gemm_mma<3><<<dim3(3072 / 256, MROWS / 128), 256, GEMM_SMEM>>>(
        ph, pWq, b_qkv, nullptr, nullptr, pq, MROWS, 3 * DIM, DIM);
    // 3. Attention (tensor-core flash) -> att fp16
    attn_mma<<<dim3(SEQ / 128, BATCH * NHEAD), 256, ATTN_SMEM>>>(pq, pat);
    // 4. Output projection + residual -> x1 (fp32)
    gemm_mma<1><<<dim3(DIM / 256, MROWS / 128), 256, GEMM_SMEM>>>(
        pat, pWo, b_o, x, px1, nullptr, MROWS, DIM, DIM);
    // 5. LN2 -> h2 (fp16)
    ln_kernel<<<MROWS, 256>>>(px1, g2, beta2, ph2);
    // 6. FC + GELU -> fc (fp16)
    gemm_mma<2><<<dim3(4 * DIM / 256, MROWS / 128), 256, GEMM_SMEM>>>(
        ph2, pWf, b_fc, nullptr, nullptr, pfc, MROWS, 4 * DIM, DIM);
    // 7. Projection + residual -> out (fp32)
    gemm_mma<1><<<dim3(DIM / 256, MROWS / 128), 256, GEMM_SMEM>>>(
        pfc, pWp, b_pr, px1, out, nullptr, MROWS, DIM, 4 * DIM);
}

// round 8
// speedup vs baseline: 6.1528x; 1.1632x over previous
#include <cuda_runtime.h>
#include <cuda_fp16.h>
#include <math.h>
#include <stdint.h>
#include <string.h>

// Problem constants
#define BATCH 2
#define SEQ   2048
#define DIM   1024
#define NHEAD 16
#define HDIM  64
#define MROWS (BATCH * SEQ)   // 4096

// ---------------------------------------------------------------------------
// Scratch (no allocations allowed -> __device__ globals)
// ---------------------------------------------------------------------------
__device__ __half g_Wqkv[3072 * 1024];
__device__ __half g_Wo  [1024 * 1024];
__device__ __half g_Wfc [4096 * 1024];
__device__ __half g_Wpr [1024 * 4096];

__device__ __half g_h  [MROWS * DIM];
__device__ __half g_qkv[MROWS * 3 * DIM];
__device__ __half g_att[MROWS * DIM];
__device__ float  g_x1 [MROWS * DIM];
__device__ __half g_h2 [MROWS * DIM];
__device__ __half g_fc [MROWS * 4 * DIM];

// ---------------------------------------------------------------------------
// PTX helpers (family-common only: cp.async, ldmatrix, mma.sync)
// ---------------------------------------------------------------------------
__device__ __forceinline__ uint32_t smem_u32(const void* p) {
    uint32_t a;
    asm("{ .reg .u64 t; cvta.to.shared.u64 t, %1; cvt.u32.u64 %0, t; }"
        : "=r"(a) : "l"(p));
    return a;
}

__device__ __forceinline__ void cp16(uint32_t dst, const void* src) {
    asm volatile("cp.async.cg.shared.global [%0], [%1], 16;"
                 :: "r"(dst), "l"(src));
}
#define CP_COMMIT() asm volatile("cp.async.commit_group;" ::: "memory")
#define CP_WAIT1()  asm volatile("cp.async.wait_group 1;" ::: "memory")
#define CP_WAIT0()  asm volatile("cp.async.wait_group 0;" ::: "memory")

__device__ __forceinline__ void ldsm4(uint32_t* r, uint32_t a) {
    asm volatile("ldmatrix.sync.aligned.m8n8.x4.shared.b16 {%0,%1,%2,%3}, [%4];"
                 : "=r"(r[0]), "=r"(r[1]), "=r"(r[2]), "=r"(r[3]) : "r"(a));
}
__device__ __forceinline__ void ldsm4t(uint32_t* r, uint32_t a) {
    asm volatile("ldmatrix.sync.aligned.m8n8.x4.trans.shared.b16 {%0,%1,%2,%3}, [%4];"
                 : "=r"(r[0]), "=r"(r[1]), "=r"(r[2]), "=r"(r[3]) : "r"(a));
}

__device__ __forceinline__ void mma16816(float* d, const uint32_t* a,
                                         uint32_t b0, uint32_t b1) {
    asm volatile(
        "mma.sync.aligned.m16n8k16.row.col.f32.f16.f16.f32 "
        "{%0,%1,%2,%3}, {%4,%5,%6,%7}, {%8,%9}, {%0,%1,%2,%3};"
        : "+f"(d[0]), "+f"(d[1]), "+f"(d[2]), "+f"(d[3])
        : "r"(a[0]), "r"(a[1]), "r"(a[2]), "r"(a[3]), "r"(b0), "r"(b1));
}

__device__ __forceinline__ uint32_t pk2h(__half a, __half b) {
    __half2 t(a, b);
    uint32_t r;
    memcpy(&r, &t, 4);
    return r;
}

// ---------------------------------------------------------------------------
// fp16 mma.sync GEMM, single pass.
// A fp16 [M,K] K-major, B fp16 [N,K] K-major.
// Block tile 128x256, K-chunk 64, 8 warps (2x4), warp tile 64x64.
// 3-stage cp.async, ONE __syncthreads per chunk, loads lead compute.
// EPI: 1 = +bias+res -> fp32; 2 = gelu(+bias) -> fp16; 3 = +bias -> fp16
// ---------------------------------------------------------------------------
#define TS 72                        // smem row stride in fp16 elems (144 bytes)
#define ROWB (TS * 2)                // 144
#define TILE_A (128 * ROWB)          // 18432 bytes
#define TILE_BB (256 * ROWB)         // 36864 bytes
#define STAGE_B (TILE_A + TILE_BB)   // 55296
#define GEMM_SMEM (3 * STAGE_B)      // 165888

template <int EPI>
__global__ __launch_bounds__(256, 1) void gemm_mma(
    const __half* __restrict__ A, const __half* __restrict__ B,
    const float* __restrict__ bias, const float* __restrict__ res,
    float* __restrict__ Co, __half* __restrict__ Ch,
    int M, int N, int K)
{
    extern __shared__ char sm_raw[];
    uint32_t sb = smem_u32(sm_raw);

    int tid  = threadIdx.x;
    int w    = tid >> 5;
    int lane = tid & 31;
    int wm   = w >> 2;               // 0..1  (64-row group)
    int wn   = w & 3;                // 0..3  (64-col group)
    int n0   = blockIdx.x * 256;
    int m0   = blockIdx.y * 128;

    const __half* srcA = A + (size_t)m0 * K;
    const __half* srcB = B + (size_t)n0 * K;

    float acc[4][8][4];
    #pragma unroll
    for (int i = 0; i < 4; i++)
        #pragma unroll
        for (int j = 0; j < 8; j++)
            #pragma unroll
            for (int q = 0; q < 4; q++) acc[i][j][q] = 0.0f;

    int nch = K >> 6;                // K/64

    // stage loader: A 128 rows + B 256 rows, 8 chunks(16B) each = 3072 cp
    auto load_stage = [&](int c, int s) {
        int k0 = c << 6;
        uint32_t stg = sb + s * STAGE_B;
        #pragma unroll
        for (int it = 0; it < 12; it++) {
            int idx = it * 256 + tid;          // 0..3071
            const __half* src;
            uint32_t dst;
            if (idx < 1024) {                  // A tile: 128 rows x 8 chunks
                int row   = idx >> 3;
                int chunk = idx & 7;
                src = srcA + (size_t)row * K + k0 + chunk * 8;
                dst = stg + (uint32_t)(row * ROWB + chunk * 16);
            } else {                           // B tile: 256 rows x 8 chunks
                int idx2  = idx - 1024;
                int row   = idx2 >> 3;
                int chunk = idx2 & 7;
                src = srcB + (size_t)row * K + k0 + chunk * 8;
                dst = stg + TILE_A + (uint32_t)(row * ROWB + chunk * 16);
            }
            cp16(dst, src);
        }
        CP_COMMIT();
    };

    load_stage(0, 0);
    if (nch > 1) load_stage(1, 1);

    int arow = wm * 64 + (lane & 15);
    uint32_t a_off = (uint32_t)(arow * ROWB) + (uint32_t)((lane >> 4) * 16);
    int bmat = lane >> 3;                 // 0..3
    int b_h  = bmat & 1;                  // k half within k16
    int b_j  = bmat >> 1;                 // n8 tile within 16-col group
    uint32_t b_off = (uint32_t)((wn * 64 + b_j * 8 + (lane & 7)) * ROWB)
                   + (uint32_t)(b_h * 16);

    for (int c = 0; c < nch; c++) {
        int s = c % 3;
        if (c + 1 < nch) { CP_WAIT1(); } else { CP_WAIT0(); }
        __syncthreads();
        // issue loads for chunk c+2 into the stage freed at iteration c-1
        if (c + 2 < nch) load_stage(c + 2, (c + 2) % 3);

        uint32_t stg = sb + s * STAGE_B;
        uint32_t pA = stg;
        uint32_t pB = stg + TILE_A;

        #pragma unroll
        for (int kk = 0; kk < 64; kk += 16) {
            uint32_t kb = (uint32_t)kk * 2;
            uint32_t ah[4][4];
            #pragma unroll
            for (int i = 0; i < 4; i++)
                ldsm4(ah[i], pA + a_off + kb + (uint32_t)(i * 16 * ROWB));
            #pragma unroll
            for (int g = 0; g < 4; g++) {          // 16-col groups
                uint32_t boff = b_off + (uint32_t)(g * 16 * ROWB) + kb;
                uint32_t bh[4];
                ldsm4(bh, pB + boff);
                int j0 = 2 * g, j1 = 2 * g + 1;
                #pragma unroll
                for (int i = 0; i < 4; i++) {
                    mma16816(acc[i][j0], ah[i], bh[0], bh[1]);
                    mma16816(acc[i][j1], ah[i], bh[2], bh[3]);
                }
            }
        }
    }

    // Epilogue
    int r0 = m0 + wm * 64 + (lane >> 2);
    int c0 = n0 + wn * 64 + (lane & 3) * 2;
    #pragma unroll
    for (int i = 0; i < 4; i++) {
        int row = r0 + i * 16;
        #pragma unroll
        for (int j = 0; j < 8; j++) {
            int col = c0 + j * 8;
            float b0 = bias[col], b1 = bias[col + 1];
            float v0 = acc[i][j][0] + b0;
            float v1 = acc[i][j][1] + b1;
            float v2 = acc[i][j][2] + b0;
            float v3 = acc[i][j][3] + b1;
            if (EPI == 1) {
                const float* rp0 = res + (size_t)row * N + col;
                const float* rp1 = res + (size_t)(row + 8) * N + col;
                v0 += rp0[0]; v1 += rp0[1];
                v2 += rp1[0]; v3 += rp1[1];
                *(float2*)(Co + (size_t)row * N + col) = make_float2(v0, v1);
                *(float2*)(Co + (size_t)(row + 8) * N + col) = make_float2(v2, v3);
            } else {
                if (EPI == 2) {
                    v0 = 0.5f * v0 * (1.0f + erff(v0 * 0.70710678118654752f));
                    v1 = 0.5f * v1 * (1.0f + erff(v1 * 0.70710678118654752f));
                    v2 = 0.5f * v2 * (1.0f + erff(v2 * 0.70710678118654752f));
                    v3 = 0.5f * v3 * (1.0f + erff(v3 * 0.70710678118654752f));
                }
                *(__half2*)(Ch + (size_t)row * N + col) =
                    __half2(__float2half(v0), __float2half(v1));
                *(__half2*)(Ch + (size_t)(row + 8) * N + col) =
                    __half2(__float2half(v2), __float2half(v3));
            }
        }
    }
}

// ---------------------------------------------------------------------------
// Fused weight prep: all 4 weights, W[K,N] fp32 -> Wt fp16 [N,K], one launch.
// Tile ranges (hard-coded shapes):
//   m0 Wqkv 1024x3072 : 96x32 tiles = 3072   [0, 3072)
//   m1 Wo   1024x1024 : 32x32 tiles = 1024   [3072, 4096)
//   m2 Wfc  1024x4096 : 128x32 tiles = 4096  [4096, 8192)
//   m3 Wpr  4096x1024 : 32x128 tiles = 4096  [8192, 12288)
// ---------------------------------------------------------------------------
__global__ __launch_bounds__(256) void wtrans_all(
    const float* __restrict__ Wq, const float* __restrict__ Wo,
    const float* __restrict__ Wf, const float* __restrict__ Wp,
    __half* __restrict__ Tq, __half* __restrict__ To,
    __half* __restrict__ Tf, __half* __restrict__ Tp)
{
    int bid = blockIdx.x;
    const float* W; __half* T; int K, N, r;
    if (bid < 3072)      { W = Wq; T = Tq; K = 1024; N = 3072; r = bid; }
    else if (bid < 4096) { W = Wo; T = To; K = 1024; N = 1024; r = bid - 3072; }
    else if (bid < 8192) { W = Wf; T = Tf; K = 1024; N = 4096; r = bid - 4096; }
    else                 { W = Wp; T = Tp; K = 4096; N = 1024; r = bid - 8192; }
    int nbx = N >> 5;
    int n0 = (r % nbx) * 32, k0 = (r / nbx) * 32;

    __shared__ float t[32][33];
    int tx = threadIdx.x & 31, ty = threadIdx.x >> 5;
    #pragma unroll
    for (int i = 0; i < 4; i++) {
        int kr = ty * 4 + i;
        t[kr][tx] = W[(size_t)(k0 + kr) * N + n0 + tx];
    }
    __syncthreads();
    #pragma unroll
    for (int i = 0; i < 4; i++) {
        int nr = ty * 4 + i;
        T[(size_t)(n0 + nr) * K + k0 + tx] = __float2half(t[tx][nr]);
    }
}

// ---------------------------------------------------------------------------
// LayerNorm -> fp16 output. One block per row, 256 threads, float4.
// ---------------------------------------------------------------------------
__global__ __launch_bounds__(256) void ln_kernel(
    const float* __restrict__ x, const float* __restrict__ g,
    const float* __restrict__ b, __half* __restrict__ y)
{
    __shared__ float sh[16];
    int row = blockIdx.x;
    int t = threadIdx.x;
    const float4* xr = (const float4*)(x + (size_t)row * DIM);
    float4 v = xr[t];
    float s  = v.x + v.y + v.z + v.w;
    float s2 = v.x*v.x + v.y*v.y + v.z*v.z + v.w*v.w;
    #pragma unroll
    for (int o = 16; o > 0; o >>= 1) {
        s  += __shfl_xor_sync(0xffffffffu, s,  o);
        s2 += __shfl_xor_sync(0xffffffffu, s2, o);
    }
    if ((t & 31) == 0) { sh[t >> 5] = s; sh[8 + (t >> 5)] = s2; }
    __syncthreads();
    if (t < 32) {
        float a  = (t < 8) ? sh[t]     : 0.0f;
        float a2 = (t < 8) ? sh[8 + t] : 0.0f;
        #pragma unroll
        for (int o = 4; o > 0; o >>= 1) {
            a  += __shfl_xor_sync(0xffffffffu, a,  o);
            a2 += __shfl_xor_sync(0xffffffffu, a2, o);
        }
        if (t == 0) { sh[0] = a; sh[1] = a2; }
    }
    __syncthreads();
    float mean = sh[0] * (1.0f / DIM);
    float var  = sh[1] * (1.0f / DIM) - mean * mean;
    float rstd = rsqrtf(var + 1e-5f);
    float4 gg = ((const float4*)g)[t];
    float4 bb = ((const float4*)b)[t];
    float o0 = (v.x - mean) * rstd * gg.x + bb.x;
    float o1 = (v.y - mean) * rstd * gg.y + bb.y;
    float o2 = (v.z - mean) * rstd * gg.z + bb.z;
    float o3 = (v.w - mean) * rstd * gg.w + bb.w;
    size_t o = (size_t)row * DIM + t * 4;
    __half2* hp = (__half2*)(y + o);
    hp[0] = __half2(__float2half(o0), __float2half(o1));
    hp[1] = __half2(__float2half(o2), __float2half(o3));
}

// ---------------------------------------------------------------------------
// Flash attention on fp16 mma.sync, single-precision-pass.
// CTA: 128 queries x one (b,h). 8 warps, 16 q-rows each. kv tiles of 64.
// ---------------------------------------------------------------------------
#define AT_ROWB   144
#define AT_TILE   (64 * AT_ROWB)     // 9216
#define AT_STAGE  (2 * AT_TILE)      // 18432 (K, V)
#define ATTN_SMEM (2 * AT_STAGE)     // 36864

__global__ __launch_bounds__(256) void attn_mma(
    const __half* __restrict__ qkv,
    __half* __restrict__ oout)
{
    extern __shared__ char sm_raw[];
    uint32_t sb = smem_u32(sm_raw);

    int tid  = threadIdx.x;
    int w    = tid >> 5;
    int lane = tid & 31;
    int qb   = (int)(gridDim.x - 1 - blockIdx.x);   // long CTAs first
    int bhid = blockIdx.y;
    int b    = bhid >> 4;
    int h    = bhid & 15;
    int q0   = qb * 128;
    const int D3 = 3 * DIM;
    size_t rowbase = (size_t)(b * SEQ) * D3 + h * 64;

    // ---- Load Q into smem (temporarily in stage area) ----
    #pragma unroll
    for (int it = 0; it < 4; it++) {
        int idx = it * 256 + tid;            // 0..1023
        int row = idx >> 3;                  // 0..127
        int c   = idx & 7;
        const __half* src = qkv + rowbase + (size_t)(q0 + row) * D3 + c * 8;
        *(uint4*)(sm_raw + row * AT_ROWB + c * 16) = *(const uint4*)src;
    }
    __syncthreads();

    uint32_t qf[4][4];
    {
        int row = w * 16 + (lane & 15);
        uint32_t boff = (uint32_t)(row * AT_ROWB) + (uint32_t)((lane >> 4) * 16);
        #pragma unroll
        for (int kk = 0; kk < 4; kk++)
            ldsm4(qf[kk], sb + boff + kk * 32);
    }
    __syncthreads();

    float m2[2] = { -1e30f, -1e30f };
    float l2[2] = { 0.0f, 0.0f };
    float oacc[8][4];
    #pragma unroll
    for (int j = 0; j < 8; j++)
        #pragma unroll
        for (int q = 0; q < 4; q++) oacc[j][q] = 0.0f;

    const __half* kv_srcs[2] = { qkv + rowbase + DIM, qkv + rowbase + 2 * DIM };

    auto load_kv = [&](int kt, int s) {
        #pragma unroll
        for (int it = 0; it < 4; it++) {
            int idx = it * 256 + tid;        // 0..1023
            int mat = idx >> 9;              // 0..1 (K, V)
            int rem = idx & 511;
            int row = rem >> 3;              // 0..63
            int c   = rem & 7;
            const __half* src =
                kv_srcs[mat] + (size_t)(kt * 64 + row) * D3 + c * 8;
            cp16(sb + s * AT_STAGE + mat * AT_TILE + row * AT_ROWB + c * 16, src);
        }
        CP_COMMIT();
    };

    int ktmax = 2 * qb + 1;
    load_kv(0, 0);

    int qrow0 = q0 + w * 16 + (lane >> 2);

    for (int kt = 0; kt <= ktmax; kt++) {
        int s = kt & 1;
        if (kt < ktmax) { load_kv(kt + 1, s ^ 1); CP_WAIT1(); }
        else            { CP_WAIT0(); }
        __syncthreads();

        bool active = (kt * 64 <= q0 + w * 16 + 15);
        if (active) {
            uint32_t kb_s = sb + s * AT_STAGE;
            uint32_t vb_s = kb_s + AT_TILE;

            float sacc[8][4];
            #pragma unroll
            for (int j = 0; j < 8; j++)
                #pragma unroll
                for (int q = 0; q < 4; q++) sacc[j][q] = 0.0f;

            int bm   = lane >> 3;
            int bkh  = bm & 1;
            int bjj  = bm >> 1;
            int brow = (lane & 7) + bjj * 8;
            #pragma unroll
            for (int jp = 0; jp < 4; jp++) {
                #pragma unroll
                for (int kk = 0; kk < 4; kk++) {
                    uint32_t off = (uint32_t)((jp * 16 + brow) * AT_ROWB)
                                 + (uint32_t)((bkh * 8 + kk * 16) * 2);
                    uint32_t khr[4];
                    ldsm4(khr, kb_s + off);
                    mma16816(sacc[2 * jp],     qf[kk], khr[0], khr[1]);
                    mma16816(sacc[2 * jp + 1], qf[kk], khr[2], khr[3]);
                }
            }

            bool needmask = (kt * 64 + 63 > q0 + w * 16);
            #pragma unroll
            for (int hh = 0; hh < 2; hh++) {
                int qrow = qrow0 + hh * 8;
                #pragma unroll
                for (int j = 0; j < 8; j++) {
                    #pragma unroll
                    for (int c = 0; c < 2; c++) {
                        float v = sacc[j][2 * hh + c] * 0.125f;
                        if (needmask) {
                            int kv = kt * 64 + j * 8 + (lane & 3) * 2 + c;
                            if (kv > qrow) v = -1e30f;
                        }
                        sacc[j][2 * hh + c] = v;
                    }
                }
                float mx = -1e30f;
                #pragma unroll
                for (int j = 0; j < 8; j++)
                    mx = fmaxf(mx, fmaxf(sacc[j][2 * hh], sacc[j][2 * hh + 1]));
                mx = fmaxf(mx, __shfl_xor_sync(0xffffffffu, mx, 1));
                mx = fmaxf(mx, __shfl_xor_sync(0xffffffffu, mx, 2));
                float mn = fmaxf(m2[hh], mx);
                float sum = 0.0f;
                #pragma unroll
                for (int j = 0; j < 8; j++) {
                    float p0 = __expf(sacc[j][2 * hh]     - mn);
                    float p1 = __expf(sacc[j][2 * hh + 1] - mn);
                    sacc[j][2 * hh]     = p0;
                    sacc[j][2 * hh + 1] = p1;
                    sum += p0 + p1;
                }
                sum += __shfl_xor_sync(0xffffffffu, sum, 1);
                sum += __shfl_xor_sync(0xffffffffu, sum, 2);
                float alpha = __expf(m2[hh] - mn);
                m2[hh] = mn;
                l2[hh] = l2[hh] * alpha + sum;
                #pragma unroll
                for (int j = 0; j < 8; j++) {
                    oacc[j][2 * hh]     *= alpha;
                    oacc[j][2 * hh + 1] *= alpha;
                }
            }

            uint32_t pah[4][4];
            #pragma unroll
            for (int kk = 0; kk < 4; kk++) {
                #pragma unroll
                for (int t = 0; t < 4; t++) {
                    int j  = 2 * kk + (t >> 1);
                    int ci = (t & 1) * 2;
                    pah[kk][t] = pk2h(__float2half(sacc[j][ci]),
                                      __float2half(sacc[j][ci + 1]));
                }
            }

            int r   = lane & 7;
            int mm  = lane >> 3;
            #pragma unroll
            for (int jp = 0; jp < 4; jp++) {
                #pragma unroll
                for (int kk = 0; kk < 4; kk++) {
                    uint32_t off = (uint32_t)((kk * 16 + r + (mm & 1) * 8) * AT_ROWB)
                                 + (uint32_t)((jp * 16 + (mm >> 1) * 8) * 2);
                    uint32_t vhr[4];
                    ldsm4t(vhr, vb_s + off);
                    mma16816(oacc[2 * jp],     pah[kk], vhr[0], vhr[1]);
                    mma16816(oacc[2 * jp + 1], pah[kk], vhr[2], vhr[3]);
                }
            }
        }
        __syncthreads();
    }

    float inv0 = 1.0f / l2[0];
    float inv1 = 1.0f / l2[1];
    size_t obase = (size_t)(b * SEQ) * DIM + h * 64;
    int row1 = q0 + w * 16 + (lane >> 2);
    int colb = (lane & 3) * 2;
    #pragma unroll
    for (int j = 0; j < 8; j++) {
        int col = j * 8 + colb;
        *(__half2*)(oout + obase + (size_t)row1 * DIM + col) =
            __half2(__float2half(oacc[j][0] * inv0), __float2half(oacc[j][1] * inv0));
        *(__half2*)(oout + obase + (size_t)(row1 + 8) * DIM + col) =
            __half2(__float2half(oacc[j][2] * inv1), __float2half(oacc[j][3] * inv1));
    }
}

// ---------------------------------------------------------------------------
// Launch
// ---------------------------------------------------------------------------
extern "C" void kernel_launch(void* const* d_in, const int* in_sizes, int n_in,
                              void* d_out, int out_size)
{
    const float* x      = (const float*)d_in[0];
    const float* W_qkv  = (const float*)d_in[1];
    const float* b_qkv  = (const float*)d_in[2];
    const float* W_o    = (const float*)d_in[3];
    const float* b_o    = (const float*)d_in[4];
    const float* W_fc   = (const float*)d_in[5];
    const float* b_fc   = (const float*)d_in[6];
    const float* W_pr   = (const float*)d_in[7];
    const float* b_pr   = (const float*)d_in[8];
    const float* g1     = (const float*)d_in[9];
    const float* beta1  = (const float*)d_in[10];
    const float* g2     = (const float*)d_in[11];
    const float* beta2  = (const float*)d_in[12];
    float* out = (float*)d_out;

    __half *pWq, *pWo, *pWf, *pWp;
    __half *ph, *pq, *pat, *ph2, *pfc;
    float *px1;
    cudaGetSymbolAddress((void**)&pWq,  g_Wqkv);
    cudaGetSymbolAddress((void**)&pWo,  g_Wo);
    cudaGetSymbolAddress((void**)&pWf,  g_Wfc);
    cudaGetSymbolAddress((void**)&pWp,  g_Wpr);
    cudaGetSymbolAddress((void**)&ph,   g_h);
    cudaGetSymbolAddress((void**)&pq,   g_qkv);
    cudaGetSymbolAddress((void**)&pat,  g_att);
    cudaGetSymbolAddress((void**)&px1,  g_x1);
    cudaGetSymbolAddress((void**)&ph2,  g_h2);
    cudaGetSymbolAddress((void**)&pfc,  g_fc);

    cudaFuncSetAttribute(attn_mma,
                         cudaFuncAttributeMaxDynamicSharedMemorySize, ATTN_SMEM);
    cudaFuncSetAttribute(gemm_mma<1>,
                         cudaFuncAttributeMaxDynamicSharedMemorySize, GEMM_SMEM);
    cudaFuncSetAttribute(gemm_mma<2>,
                         cudaFuncAttributeMaxDynamicSharedMemorySize, GEMM_SMEM);
    cudaFuncSetAttribute(gemm_mma<3>,
                         cudaFuncAttributeMaxDynamicSharedMemorySize, GEMM_SMEM);

    // Weight prep (fused: transpose + fp16 convert, single launch)
    wtrans_all<<<12288, 256>>>(W_qkv, W_o, W_fc, W_pr, pWq, pWo, pWf, pWp);

    // 1. LN1 -> h (fp16)
    ln_kernel<<<MROWS, 256>>>(x, g1, beta1, ph);
    // 2. QKV projection -> fp16
    gemm_mma<3><<<dim3(3072 / 256, MROWS / 128), 256, GEMM_SMEM>>>(
        ph, pWq, b_qkv, nullptr, nullptr, pq, MROWS, 3 * DIM, DIM);
    // 3. Attention (tensor-core flash) -> att fp16
    attn_mma<<<dim3(SEQ / 128, BATCH * NHEAD), 256, ATTN_SMEM>>>(pq, pat);
    // 4. Output projection + residual -> x1 (fp32)
    gemm_mma<1><<<dim3(DIM / 256, MROWS / 128), 256, GEMM_SMEM>>>(
        pat, pWo, b_o, x, px1, nullptr, MROWS, DIM, DIM);
    // 5. LN2 -> h2 (fp16)
    ln_kernel<<<MROWS, 256>>>(px1, g2, beta2, ph2);
    // 6. FC + GELU -> fc (fp16)
    gemm_mma<2><<<dim3(4 * DIM / 256, MROWS / 128), 256, GEMM_SMEM>>>(
        ph2, pWf, b_fc, nullptr, nullptr, pfc, MROWS, 4 * DIM, DIM);
    // 7. Projection + residual -> out (fp32)
    gemm_mma<1><<<dim3(DIM / 256, MROWS / 128), 256, GEMM_SMEM>>>(
        pfc, pWp, b_pr, px1, out, nullptr, MROWS, DIM, 4 * DIM);
}